// round 13
// baseline (speedup 1.0000x reference)
#include <cuda_runtime.h>
#include <cuda_bf16.h>
#include <math.h>
#include <stdint.h>

// ---------------- problem constants ----------------
constexpr int BATCH = 4;
constexpr int SEQ   = 4096;
constexpr int DIM   = 256;
constexpr int DFF   = 1024;
constexpr int NTOK  = BATCH * SEQ;                 // 16384
constexpr size_t TXT_N = (size_t)NTOK * DIM;       // 4,194,304
constexpr int IMG_N = BATCH * 196 * DIM;           // 200,704

// ---------------- scratch (device globals; no allocs allowed) ----------------
__device__ __align__(16) __nv_bfloat16 g_textbf[4194304];
__device__ __align__(16) __nv_bfloat16 g_Qbf [4194304];
__device__ __align__(16) __nv_bfloat16 g_Kbf [4194304];
__device__ __align__(16) __nv_bfloat16 g_Vbf [4194304];
__device__ __align__(16) __nv_bfloat16 g_Vtbf[4194304];
__device__ __align__(16) __nv_bfloat16 g_SKbf[4194304];
__device__ __align__(16) __nv_bfloat16 g_SKtbf[4194304];
__device__ __align__(16) __nv_bfloat16 g_Hbf [4194304];
__device__ __align__(16) __nv_bfloat16 g_FFbf[16777216];
__device__ __align__(16) __nv_bfloat16 g_Wqkvbf[3 * DIM * DIM];   // [768, 256]
__device__ __align__(16) __nv_bfloat16 g_W1bf[DFF * DIM];
__device__ __align__(16) __nv_bfloat16 g_W2bf[DIM * DFF];
__device__ __align__(16) __nv_bfloat16 g_G2bf[BATCH * DIM * DIM];
__device__ float g_bqkv[3 * DIM];
__device__ float g_Osum [4194304];                 // attn + text (fp32)
__device__ float g_M2sum[4194304];                 // mlp + text (fp32)
__device__ float g_G2 [BATCH * DIM * DIM];
__device__ float g_sacc[4];                        // [sum1, ss1, sum2, ss2]
__device__ float g_stats[4];                       // [mu1, r1, mu2, r2]
__device__ float g_P [BATCH * 4 * DIM];
__device__ float g_pp[BATCH * 16 * DIM];
__device__ float g_vpp[BATCH * 32 * DIM];
__device__ float g_Vsum[BATCH * DIM];
__device__ float g_sksum[BATCH * DIM];
__device__ float g_rowscale[NTOK];

// ================= helpers =================
__device__ __forceinline__ uint32_t smem_u32(const void* p) {
    uint32_t a;
    asm("{ .reg .u64 t; cvta.to.shared.u64 t, %1; cvt.u32.u64 %0, t; }" : "=r"(a) : "l"(p));
    return a;
}
#define CP16(dst, src) \
    asm volatile("cp.async.cg.shared.global [%0], [%1], 16;" :: "r"(dst), "l"(src))
#define CP_COMMIT() asm volatile("cp.async.commit_group;" ::: "memory")
#define CP_WAIT(n)  asm volatile("cp.async.wait_group %0;" :: "n"(n) : "memory")

// mma.sync m16n8k16 bf16 (row.col): D += A*B
__device__ __forceinline__ void mma16(float* c, uint32_t a0, uint32_t a1,
                                      uint32_t a2, uint32_t a3, uint32_t b0, uint32_t b1) {
    asm volatile(
        "mma.sync.aligned.m16n8k16.row.col.f32.bf16.bf16.f32 "
        "{%0,%1,%2,%3}, {%4,%5,%6,%7}, {%8,%9}, {%0,%1,%2,%3};\n"
        : "+f"(c[0]), "+f"(c[1]), "+f"(c[2]), "+f"(c[3])
        : "r"(a0), "r"(a1), "r"(a2), "r"(a3), "r"(b0), "r"(b1));
}
__device__ __forceinline__ uint32_t pack_bf2(float x, float y) {
    __nv_bfloat162 h = __float22bfloat162_rn(make_float2(x, y));
    return *(uint32_t*)&h;
}

// ================= bf16 tensor-core GEMM (general) ============================
// C[r,c] = rowscale[r]*(alpha*sum_k A[r,k]B[c,k] + bias[c]) (+relu)(+resid)
// split-K atomic fp32 out, bf16 out, fused LN stats, fused QKV column routing.
constexpr int BFBK = 64;
constexpr int BSTR = 36;                            // words per smem row (32+pad)
constexpr int BF_STAGE = 128 * BSTR * 4;            // 18432
constexpr int BF_SMEM = 4 * BF_STAGE;               // 73728

__device__ __forceinline__ void load_stage_bf(
    uint32_t smA, uint32_t smB,
    const __nv_bfloat16* __restrict__ Ab, const __nv_bfloat16* __restrict__ Bb,
    int K, int k0, int tid)
{
#pragma unroll
    for (int it = 0; it < 4; it++) {
        int idx = tid + it * 256;                    // 0..1023
        int row = idx >> 3, seg = idx & 7;
        CP16(smA + (uint32_t)(row * BSTR + seg * 4) * 4,
             Ab + (size_t)row * K + k0 + seg * 8);
    }
#pragma unroll
    for (int it = 0; it < 4; it++) {
        int idx = tid + it * 256;
        int row = idx >> 3, seg = idx & 7;
        CP16(smB + (uint32_t)(row * BSTR + seg * 4) * 4,
             Bb + (size_t)row * K + k0 + seg * 8);
    }
}

__global__ void __launch_bounds__(256) bf_gemm(
    const __nv_bfloat16* __restrict__ A, const __nv_bfloat16* __restrict__ B,
    void* __restrict__ C, int M, int N, int K, int Kloc, int kchunks,
    long long sA, long long sB, long long sC,
    float alpha, const float* __restrict__ bias, long long sBias, int relu,
    const float* __restrict__ rowscale, int atomic_out, int out_bf,
    const float* __restrict__ resid, float* __restrict__ stats_acc,
    void* __restrict__ C2, void* __restrict__ C3, int qkv)
{
    extern __shared__ char smem[];
    const int tid = threadIdx.x;
    const int wid = tid >> 5, lane = tid & 31;
    const int wm = wid & 3, wn = wid >> 2;
    const int g = lane >> 2, tg = lane & 3, t2 = tg << 1;
    const int bx = blockIdx.x, by = blockIdx.y;
    const int bz = blockIdx.z / kchunks;
    const int kc = blockIdx.z % kchunks;
    const int m0 = by * 128, n0 = bx * 128;
    const __nv_bfloat16* Ab = A + (size_t)bz * sA + (size_t)m0 * K + (size_t)kc * Kloc;
    const __nv_bfloat16* Bb = B + (size_t)bz * sB + (size_t)n0 * K + (size_t)kc * Kloc;

    const uint32_t sbase = smem_u32(smem);
    const uint32_t smA[2] = { sbase, sbase + BF_STAGE };
    const uint32_t smB[2] = { sbase + 2 * BF_STAGE, sbase + 3 * BF_STAGE };

    float acc[2][8][4];
#pragma unroll
    for (int i = 0; i < 2; i++)
#pragma unroll
        for (int j = 0; j < 8; j++)
#pragma unroll
            for (int v = 0; v < 4; v++) acc[i][j][v] = 0.f;

    const int KT = Kloc / BFBK;
    load_stage_bf(smA[0], smB[0], Ab, Bb, K, 0, tid);
    CP_COMMIT();

    for (int kt = 0; kt < KT; kt++) {
        const int cur = kt & 1;
        if (kt + 1 < KT) {
            load_stage_bf(smA[cur ^ 1], smB[cur ^ 1], Ab, Bb, K, (kt + 1) * BFBK, tid);
            CP_COMMIT();
            CP_WAIT(1);
        } else {
            CP_WAIT(0);
        }
        __syncthreads();

        const uint32_t* As = (const uint32_t*)(smem + (size_t)cur * BF_STAGE);
        const uint32_t* Bs = (const uint32_t*)(smem + (size_t)(2 + cur) * BF_STAGE);
#pragma unroll
        for (int step = 0; step < 4; step++) {
            const int kw = step * 8;
            uint32_t afr[2][4];
#pragma unroll
            for (int i = 0; i < 2; i++) {
                int r = wm * 32 + i * 16 + g;
                afr[i][0] = As[r * BSTR + kw + tg];
                afr[i][1] = As[(r + 8) * BSTR + kw + tg];
                afr[i][2] = As[r * BSTR + kw + tg + 4];
                afr[i][3] = As[(r + 8) * BSTR + kw + tg + 4];
            }
#pragma unroll
            for (int j = 0; j < 8; j++) {
                int n = wn * 64 + j * 8 + g;
                uint32_t b0 = Bs[n * BSTR + kw + tg];
                uint32_t b1 = Bs[n * BSTR + kw + tg + 4];
#pragma unroll
                for (int i = 0; i < 2; i++)
                    mma16(acc[i][j], afr[i][0], afr[i][1], afr[i][2], afr[i][3], b0, b1);
            }
        }
        __syncthreads();
    }

    const float* bp = bias ? bias + (size_t)bz * sBias : nullptr;
    const float* rs = rowscale ? rowscale + (size_t)bz * M : nullptr;
    const float* rp = resid ? resid + (size_t)bz * sC : nullptr;
    float lsum = 0.f, lss = 0.f;
#pragma unroll
    for (int i = 0; i < 2; i++) {
        int r = m0 + wm * 32 + i * 16 + g;
#pragma unroll
        for (int j = 0; j < 8; j++) {
            int c = n0 + wn * 64 + j * 8 + t2;
            float2 v0, v1;
            v0.x = acc[i][j][0] * alpha; v0.y = acc[i][j][1] * alpha;
            v1.x = acc[i][j][2] * alpha; v1.y = acc[i][j][3] * alpha;
            if (bp) {
                float bb0 = __ldg(bp + c), bb1 = __ldg(bp + c + 1);
                v0.x += bb0; v0.y += bb1;
                v1.x += bb0; v1.y += bb1;
            }
            if (relu) {
                v0.x = fmaxf(v0.x, 0.f); v0.y = fmaxf(v0.y, 0.f);
                v1.x = fmaxf(v1.x, 0.f); v1.y = fmaxf(v1.y, 0.f);
            }
            if (rs) {
                float s0 = rs[r], s1 = rs[r + 8];
                v0.x *= s0; v0.y *= s0;
                v1.x *= s1; v1.y *= s1;
            }
            if (rp) {
                v0.x += __ldg(rp + (size_t)r * N + c);
                v0.y += __ldg(rp + (size_t)r * N + c + 1);
                v1.x += __ldg(rp + (size_t)(r + 8) * N + c);
                v1.y += __ldg(rp + (size_t)(r + 8) * N + c + 1);
                lsum += v0.x + v0.y + v1.x + v1.y;
                lss  += v0.x * v0.x + v0.y * v0.y + v1.x * v1.x + v1.y * v1.y;
            }
            if (atomic_out) {
                float* Cb = (float*)C + (size_t)bz * sC;
                atomicAdd(Cb + (size_t)r * N + c,     v0.x);
                atomicAdd(Cb + (size_t)r * N + c + 1, v0.y);
                atomicAdd(Cb + (size_t)(r + 8) * N + c,     v1.x);
                atomicAdd(Cb + (size_t)(r + 8) * N + c + 1, v1.y);
            } else if (out_bf) {
                void* base = C;
                int Nout = N, cc = c;
                if (qkv) {
                    int sel = c >> 8;
                    base = (sel == 0) ? C : (sel == 1) ? C2 : C3;
                    Nout = 256;
                    cc = c & 255;
                }
                uint32_t* cb = (uint32_t*)((__nv_bfloat16*)base + (size_t)bz * sC);
                cb[((size_t)r * Nout + cc) >> 1]       = pack_bf2(v0.x, v0.y);
                cb[((size_t)(r + 8) * Nout + cc) >> 1] = pack_bf2(v1.x, v1.y);
            } else {
                float* Cb = (float*)C + (size_t)bz * sC;
                *(float2*)(Cb + (size_t)r * N + c)       = v0;
                *(float2*)(Cb + (size_t)(r + 8) * N + c) = v1;
            }
        }
    }
    if (stats_acc) {
        __shared__ float s_sum[256], s_ss[256];
        s_sum[tid] = lsum; s_ss[tid] = lss;
        __syncthreads();
        for (int o = 128; o; o >>= 1) {
            if (tid < o) { s_sum[tid] += s_sum[tid + o]; s_ss[tid] += s_ss[tid + o]; }
            __syncthreads();
        }
        if (tid == 0) {
            atomicAdd(&stats_acc[0], s_sum[0]);
            atomicAdd(&stats_acc[1], s_ss[0]);
        }
    }
}

// ---------------- batched fp32 -> bf16 conversions (one launch) ----------------
constexpr int CV_T0 = 4194304;                       // text
constexpr int CV_T1 = CV_T0 + 3 * 65536;             // Wq|Wk|Wv -> Wqkv
constexpr int CV_T2 = CV_T1 + 262144;                // W1
constexpr int CV_T3 = CV_T2 + 262144;                // W2 (total 4915200)

__global__ void convert_all(
    const float* __restrict__ text, const float* __restrict__ Wq,
    const float* __restrict__ Wk, const float* __restrict__ Wv,
    const float* __restrict__ W1, const float* __restrict__ W2,
    __nv_bfloat16* __restrict__ textbf, __nv_bfloat16* __restrict__ Wqkvbf,
    __nv_bfloat16* __restrict__ W1bf, __nv_bfloat16* __restrict__ W2bf)
{
    int i = blockIdx.x * 256 + threadIdx.x;
    if (i < CV_T0) {
        textbf[i] = __float2bfloat16(text[i]);
    } else if (i < CV_T1) {
        int j = i - CV_T0;                           // 0..196607
        const float* src = (j < 65536) ? Wq : (j < 131072) ? Wk : Wv;
        Wqkvbf[j] = __float2bfloat16(src[j & 65535]);
    } else if (i < CV_T2) {
        W1bf[i - CV_T1] = __float2bfloat16(W1[i - CV_T1]);
    } else if (i < CV_T3) {
        W2bf[i - CV_T2] = __float2bfloat16(W2[i - CV_T2]);
    }
}

__global__ void f2bf(const float* __restrict__ src, __nv_bfloat16* __restrict__ dst, int n) {
    int i = blockIdx.x * 256 + threadIdx.x;
    if (i < n) dst[i] = __float2bfloat16(src[i]);
}

// zero G2 + stats accumulators + build concatenated qkv bias (one launch)
__global__ void zero_all(float* __restrict__ G2, float* __restrict__ sacc,
                         const float* __restrict__ bq, const float* __restrict__ bk,
                         const float* __restrict__ bv, float* __restrict__ bqkv, int nG2) {
    int i = blockIdx.x * 256 + threadIdx.x;
    if (i < nG2) G2[i] = 0.f;
    if (i < 4) sacc[i] = 0.f;
    if (i < 3 * DIM) {
        const float* src = (i < DIM) ? bq : (i < 2 * DIM) ? bk : bv;
        bqkv[i] = src[i & (DIM - 1)];
    }
}

// ---------------- bf16 transpose: Xt[b,d,s] = X[b,s,d] ----------------
__global__ void transpose_bf(const __nv_bfloat16* __restrict__ X,
                             __nv_bfloat16* __restrict__ Xt) {
    __shared__ __nv_bfloat16 t[32][34];
    int b = blockIdx.z;
    int s0 = blockIdx.x * 32, d0 = blockIdx.y * 32;
    const __nv_bfloat16* Xb = X + (size_t)b * SEQ * DIM;
    __nv_bfloat16* Xtb = Xt + (size_t)b * SEQ * DIM;
    int x = threadIdx.x, y = threadIdx.y;
#pragma unroll
    for (int i = 0; i < 32; i += 8)
        t[y + i][x] = Xb[(size_t)(s0 + y + i) * DIM + d0 + x];
    __syncthreads();
#pragma unroll
    for (int i = 0; i < 32; i += 8)
        Xtb[(size_t)(d0 + y + i) * SEQ + s0 + x] = t[x][y + i];
}

// ---------------- V column sums (bf16 in, fp32 accum) ------------------
__global__ void vsum_partial(const __nv_bfloat16* __restrict__ V, float* __restrict__ vpp) {
    int ch = blockIdx.x, b = blockIdx.y, d = threadIdx.x;
    const __nv_bfloat16* Vb = V + (size_t)b * SEQ * DIM;
    float s = 0.f;
    for (int ss = ch * 128; ss < ch * 128 + 128; ss++)
        s += __bfloat162float(Vb[(size_t)ss * DIM + d]);
    vpp[((size_t)b * 32 + ch) * DIM + d] = s;
}
__global__ void vsum_combine(const float* __restrict__ vpp, float* __restrict__ Vsum) {
    int b = blockIdx.x, d = threadIdx.x;
    float s = 0.f;
    for (int ch = 0; ch < 32; ch++) s += vpp[((size_t)b * 32 + ch) * DIM + d];
    Vsum[b * DIM + d] = s;
}

// ---------------- sksum[b,d] = row sums of SKt (bf16) ------------
__global__ void sksum_kernel(const __nv_bfloat16* __restrict__ SKt, float* __restrict__ sksum) {
    int bid = blockIdx.x;                           // b*DIM + d
    const __nv_bfloat16* row = SKt + (size_t)bid * SEQ;
    int tid = threadIdx.x;
    float s = 0.f;
    for (int i = tid; i < SEQ; i += 256) s += __bfloat162float(row[i]);
    __shared__ float red[256];
    red[tid] = s;
    __syncthreads();
    for (int o = 128; o; o >>= 1) {
        if (tid < o) red[tid] += red[tid + o];
        __syncthreads();
    }
    if (tid == 0) sksum[bid] = red[0];
}

// ---------------- rowscale = 1/(SEQ + q.sksum/16), q in bf16 ---------
__global__ void rowdiv_kernel(const __nv_bfloat16* __restrict__ Q,
                              const float* __restrict__ sksum,
                              float* __restrict__ rowscale) {
    int wid = threadIdx.x >> 5, lane = threadIdx.x & 31;
    int row = blockIdx.x * 8 + wid;
    int b = row >> 12;
    const uint32_t* q = (const uint32_t*)(Q + (size_t)row * DIM);
    const float* sk = sksum + b * DIM;
    float s = 0.f;
#pragma unroll
    for (int k = 0; k < 4; k++) {
        int w = lane + k * 32;
        __nv_bfloat162 h = *(const __nv_bfloat162*)&q[w];
        s += __bfloat162float(h.x) * sk[2 * w] + __bfloat162float(h.y) * sk[2 * w + 1];
    }
#pragma unroll
    for (int o = 16; o; o >>= 1) s += __shfl_xor_sync(0xffffffffu, s, o);
    if (lane == 0) rowscale[row] = 1.f / ((float)SEQ + s * 0.0625f);
}

// ---------------- prefix sums of K rows (bf16 K, analytic sparse@K) ----------
__global__ void prefix_partial(const __nv_bfloat16* __restrict__ Kmat, float* __restrict__ pp) {
    int ch = blockIdx.x, b = blockIdx.y, d = threadIdx.x;
    int s0 = ch * 128;
    int s1 = min(s0 + 128, 2047);
    const __nv_bfloat16* Kb = Kmat + (size_t)b * SEQ * DIM;
    float s = 0.f;
    for (int ss = s0; ss < s1; ss++) s += __bfloat162float(Kb[(size_t)ss * DIM + d]);
    pp[((size_t)b * 16 + ch) * DIM + d] = s;
}

__global__ void prefix_combine(const __nv_bfloat16* __restrict__ Kmat,
                               const float* __restrict__ pp, float* __restrict__ P) {
    int b = blockIdx.x, d = threadIdx.x;
    const __nv_bfloat16* Kb = Kmat + (size_t)b * SEQ * DIM;
    float s = 0.f;
    for (int ch = 0; ch < 16; ch++) s += pp[((size_t)b * 16 + ch) * DIM + d];
    float p2047 = s;
    float p2048 = p2047 + __bfloat162float(Kb[(size_t)2047 * DIM + d]);
    float p2049 = p2048 + __bfloat162float(Kb[(size_t)2048 * DIM + d]);
    float p2052 = p2049 + __bfloat162float(Kb[(size_t)2049 * DIM + d])
                        + __bfloat162float(Kb[(size_t)2050 * DIM + d])
                        + __bfloat162float(Kb[(size_t)2051 * DIM + d]);
    float* Pb = P + (size_t)b * 4 * DIM;
    Pb[0 * DIM + d] = p2047;
    Pb[1 * DIM + d] = p2048;
    Pb[2 * DIM + d] = p2049;
    Pb[3 * DIM + d] = p2052;
}

__global__ void sk_kernel(const __nv_bfloat16* __restrict__ Kmat, const float* __restrict__ P,
                          __nv_bfloat16* __restrict__ SK,
                          float A3, float B3, float A4, float B4, float A5, float B5) {
    int i = blockIdx.x, b = blockIdx.y, d = threadIdx.x;
    const __nv_bfloat16* Kb = Kmat + (size_t)b * SEQ * DIM;
    int lo = max(i - 2, 0), hi = min(i + 2, SEQ - 1);
    int n = hi - lo + 1;
    float band = 0.f;
    for (int j = lo; j <= hi; j++) band += __bfloat162float(Kb[(size_t)j * DIM + d]);
    const float* Pb = P + (size_t)b * 4 * DIM;
    float off;
    if (i <= 2048) off = Pb[3 * DIM + d] - band;
    else           off = Pb[(5 - n) * DIM + d];
    float a, bb;
    if (n == 5)      { a = A5; bb = B5; }
    else if (n == 4) { a = A4; bb = B4; }
    else             { a = A3; bb = B3; }
    SK[((size_t)b * SEQ + i) * DIM + d] = __float2bfloat16(a * band + bb * off);
}

// ---------------- LN finalize (stats from fused accumulators) ----------------
__global__ void ln_combine2(const float* __restrict__ sacc, float* __restrict__ stats, int which) {
    double n = (double)TXT_N;
    double mu = (double)sacc[which * 2] / n;
    double var = (double)sacc[which * 2 + 1] / n - mu * mu;
    stats[which * 2]     = (float)mu;
    stats[which * 2 + 1] = (float)(1.0 / sqrt(var + 1e-6));
}

// x already contains (value + residual)
__global__ void ln_apply1(const float* __restrict__ x,
                          const float* __restrict__ g, const float* __restrict__ bta,
                          const float* __restrict__ stats, int which, float* __restrict__ out) {
    size_t i = (size_t)blockIdx.x * 256 + threadIdx.x;
    float mu = stats[which * 2], r = stats[which * 2 + 1];
    out[i] = (x[i] - mu) * r * g[i] + bta[i];
}

__global__ void ln_apply1_bf(const float* __restrict__ x,
                             const float* __restrict__ g, const float* __restrict__ bta,
                             const float* __restrict__ stats, int which,
                             __nv_bfloat16* __restrict__ out) {
    size_t i = (size_t)blockIdx.x * 256 + threadIdx.x;
    float mu = stats[which * 2], r = stats[which * 2 + 1];
    out[i] = __float2bfloat16((x[i] - mu) * r * g[i] + bta[i]);
}

__global__ void copy_img(const float* __restrict__ src, float* __restrict__ dst, int n) {
    int i = blockIdx.x * 256 + threadIdx.x;
    if (i < n) dst[i] = src[i];
}

// ---------------- launch ----------------
extern "C" void kernel_launch(void* const* d_in, const int* in_sizes, int n_in,
                              void* d_out, int out_size) {
    const float* text  = (const float*)d_in[0];
    const float* image = (const float*)d_in[1];
    const float* Wq = (const float*)d_in[2];
    const float* bq = (const float*)d_in[3];
    const float* Wk = (const float*)d_in[4];
    const float* bk = (const float*)d_in[5];
    const float* Wv = (const float*)d_in[6];
    const float* bv = (const float*)d_in[7];
    const float* W1 = (const float*)d_in[8];
    const float* b1 = (const float*)d_in[9];
    const float* W2 = (const float*)d_in[10];
    const float* b2 = (const float*)d_in[11];
    const float* gamma = (const float*)d_in[12];
    const float* beta  = (const float*)d_in[13];
    float* out = (float*)d_out;

    float *Osum, *M2sum, *G2, *sacc, *stats, *P, *pp, *vpp, *Vsum, *sksum, *rowscale, *bqkv;
    __nv_bfloat16 *textbf, *Qbf, *Kbf, *Vbf, *Vtbf, *SKbf, *SKtbf, *Hbf, *FFbf;
    __nv_bfloat16 *Wqkvbf, *W1bf, *W2bf, *G2bf;
    cudaGetSymbolAddress((void**)&textbf, g_textbf);
    cudaGetSymbolAddress((void**)&Qbf,  g_Qbf);
    cudaGetSymbolAddress((void**)&Kbf,  g_Kbf);
    cudaGetSymbolAddress((void**)&Vbf,  g_Vbf);
    cudaGetSymbolAddress((void**)&Vtbf, g_Vtbf);
    cudaGetSymbolAddress((void**)&SKbf, g_SKbf);
    cudaGetSymbolAddress((void**)&SKtbf, g_SKtbf);
    cudaGetSymbolAddress((void**)&Hbf,  g_Hbf);
    cudaGetSymbolAddress((void**)&FFbf, g_FFbf);
    cudaGetSymbolAddress((void**)&Wqkvbf, g_Wqkvbf);
    cudaGetSymbolAddress((void**)&W1bf, g_W1bf);
    cudaGetSymbolAddress((void**)&W2bf, g_W2bf);
    cudaGetSymbolAddress((void**)&G2bf, g_G2bf);
    cudaGetSymbolAddress((void**)&bqkv, g_bqkv);
    cudaGetSymbolAddress((void**)&Osum, g_Osum);
    cudaGetSymbolAddress((void**)&M2sum, g_M2sum);
    cudaGetSymbolAddress((void**)&G2,  g_G2);
    cudaGetSymbolAddress((void**)&sacc, g_sacc);
    cudaGetSymbolAddress((void**)&stats, g_stats);
    cudaGetSymbolAddress((void**)&P,   g_P);
    cudaGetSymbolAddress((void**)&pp,  g_pp);
    cudaGetSymbolAddress((void**)&vpp, g_vpp);
    cudaGetSymbolAddress((void**)&Vsum, g_Vsum);
    cudaGetSymbolAddress((void**)&sksum, g_sksum);
    cudaGetSymbolAddress((void**)&rowscale, g_rowscale);

    static int smem_set = 0;
    if (!smem_set) {
        cudaFuncSetAttribute(bf_gemm, cudaFuncAttributeMaxDynamicSharedMemorySize, BF_SMEM);
        smem_set = 1;
    }

    // sparse-softmax coefficients
    double e = exp(1.0);
    float A[6], Bc[6];
    for (int n = 3; n <= 5; n++) {
        double Z = n * e + (double)(SEQ - n);
        A[n]  = (float)(e / Z);
        Bc[n] = (float)(1.0 / Z);
    }

    // conversions to bf16 (one launch) + zero/bias-concat (one launch)
    convert_all<<<CV_T3 / 256, 256>>>(text, Wq, Wk, Wv, W1, W2,
                                      textbf, Wqkvbf, W1bf, W2bf);
    zero_all<<<(BATCH * DIM * DIM + 255) / 256, 256>>>(G2, sacc, bq, bk, bv, bqkv,
                                                       BATCH * DIM * DIM);

    // fused QKV projection: [16384, 768] routed into Qbf/Kbf/Vbf
    bf_gemm<<<dim3(6, 128, 1), 256, BF_SMEM>>>(textbf, Wqkvbf, Qbf,
        NTOK, 3 * DIM, DIM, DIM, 1, 0, 0, 0,
        1.f, bqkv, 0, 0, nullptr, 0, 1, nullptr, nullptr, Kbf, Vbf, 1);

    // Vt and Vsum
    transpose_bf<<<dim3(128, 8, BATCH), dim3(32, 8)>>>(Vbf, Vtbf);
    vsum_partial<<<dim3(32, BATCH), 256>>>(Vbf, vpp);
    vsum_combine<<<BATCH, 256>>>(vpp, Vsum);

    // analytic sparse @ K -> SKbf, then SKtbf and sksum
    prefix_partial<<<dim3(16, BATCH), 256>>>(Kbf, pp);
    prefix_combine<<<BATCH, 256>>>(Kbf, pp, P);
    sk_kernel<<<dim3(SEQ, BATCH), 256>>>(Kbf, P, SKbf, A[3], Bc[3], A[4], Bc[4], A[5], Bc[5]);
    transpose_bf<<<dim3(128, 8, BATCH), dim3(32, 8)>>>(SKbf, SKtbf);
    sksum_kernel<<<BATCH * DIM, 256>>>(SKtbf, sksum);

    // rowscale = 1/(SEQ + q.sksum/16)
    rowdiv_kernel<<<NTOK / 8, 256>>>(Qbf, sksum, rowscale);

    // G2[b,e,d] = sum_j V[j,e] SK[j,d]  (split-K=16, atomic fp32), then bf16
    bf_gemm<<<dim3(2, 2, BATCH * 16), 256, BF_SMEM>>>(Vtbf, SKtbf, G2,
        DIM, DIM, SEQ, SEQ / 16, 16,
        (long long)DIM * SEQ, (long long)DIM * SEQ, (long long)DIM * DIM,
        1.f, nullptr, 0, 0, nullptr, 1, 0, nullptr, nullptr, nullptr, nullptr, 0);
    f2bf<<<(BATCH * DIM * DIM + 255) / 256, 256>>>(G2, G2bf, BATCH * DIM * DIM);

    // Osum = (Vsum + Q@G2^T/16)*rowscale + text, with fused LN1 stats
    bf_gemm<<<dim3(2, 32, BATCH), 256, BF_SMEM>>>(Qbf, G2bf, Osum,
        SEQ, DIM, DIM, DIM, 1,
        (long long)SEQ * DIM, (long long)DIM * DIM, (long long)SEQ * DIM,
        0.0625f, Vsum, DIM, 0, rowscale, 0, 0, text, &sacc[0], nullptr, nullptr, 0);

    // LN1 finalize -> Hbf
    ln_combine2<<<1, 1>>>(sacc, stats, 0);
    ln_apply1_bf<<<NTOK, 256>>>(Osum, gamma, beta, stats, 0, Hbf);

    // MLP (bf16 operands, fp32 accumulate); MLP2 fuses +text and LN2 stats
    bf_gemm<<<dim3(8, 128, 1), 256, BF_SMEM>>>(Hbf, W1bf, FFbf, NTOK, DFF, DIM, DIM, 1,
        0, 0, 0, 1.f, b1, 0, 1, nullptr, 0, 1, nullptr, nullptr, nullptr, nullptr, 0);
    bf_gemm<<<dim3(2, 128, 1), 256, BF_SMEM>>>(FFbf, W2bf, M2sum, NTOK, DIM, DFF, DFF, 1,
        0, 0, 0, 1.f, b2, 0, 0, nullptr, 0, 0, text, &sacc[2], nullptr, nullptr, 0);

    // LN2 finalize -> out
    ln_combine2<<<1, 1>>>(sacc, stats, 1);
    ln_apply1<<<NTOK, 256>>>(M2sum, gamma, beta, stats, 1, out);

    // image passthrough
    if (out_size >= (int)TXT_N + IMG_N) {
        copy_img<<<(IMG_N + 255) / 256, 256>>>(image, out + TXT_N, IMG_N);
    }
}

// round 14
// speedup vs baseline: 1.0010x; 1.0010x over previous
#include <cuda_runtime.h>
#include <cuda_bf16.h>
#include <math.h>
#include <stdint.h>

// ---------------- problem constants ----------------
constexpr int BATCH = 4;
constexpr int SEQ   = 4096;
constexpr int DIM   = 256;
constexpr int DFF   = 1024;
constexpr int NTOK  = BATCH * SEQ;                 // 16384
constexpr size_t TXT_N = (size_t)NTOK * DIM;       // 4,194,304
constexpr int IMG_N = BATCH * 196 * DIM;           // 200,704

// ---------------- scratch (device globals; no allocs allowed) ----------------
__device__ __align__(16) __nv_bfloat16 g_textbf[4194304];
__device__ __align__(16) __nv_bfloat16 g_Qbf [4194304];
__device__ __align__(16) __nv_bfloat16 g_Kbf [4194304];
__device__ __align__(16) __nv_bfloat16 g_Vbf [4194304];
__device__ __align__(16) __nv_bfloat16 g_Vtbf[4194304];
__device__ __align__(16) __nv_bfloat16 g_SKbf[4194304];
__device__ __align__(16) __nv_bfloat16 g_SKtbf[4194304];
__device__ __align__(16) __nv_bfloat16 g_Hbf [4194304];
__device__ __align__(16) __nv_bfloat16 g_FFbf[16777216];
__device__ __align__(16) __nv_bfloat16 g_Wqkvbf[3 * DIM * DIM];   // [768, 256]
__device__ __align__(16) __nv_bfloat16 g_W1bf[DFF * DIM];
__device__ __align__(16) __nv_bfloat16 g_W2bf[DIM * DFF];
__device__ __align__(16) __nv_bfloat16 g_G2bf[BATCH * DIM * DIM];
__device__ float g_bqkv[3 * DIM];
__device__ float g_Osum [4194304];                 // attn + text (fp32)
__device__ float g_M2sum[4194304];                 // mlp + text (fp32)
__device__ float g_G2 [BATCH * DIM * DIM];
__device__ float g_sacc[4];                        // [sum1, ss1, sum2, ss2]
__device__ float g_stats[4];                       // [mu1, r1, mu2, r2]
__device__ float g_P [BATCH * 4 * DIM];
__device__ float g_pp[BATCH * 16 * DIM];
__device__ float g_vpp[BATCH * 32 * DIM];
__device__ float g_spp[BATCH * 32 * DIM];
__device__ float g_Vsum[BATCH * DIM];
__device__ float g_sksum[BATCH * DIM];
__device__ float g_rowscale[NTOK];

// ================= helpers =================
__device__ __forceinline__ uint32_t smem_u32(const void* p) {
    uint32_t a;
    asm("{ .reg .u64 t; cvta.to.shared.u64 t, %1; cvt.u32.u64 %0, t; }" : "=r"(a) : "l"(p));
    return a;
}
#define CP16(dst, src) \
    asm volatile("cp.async.cg.shared.global [%0], [%1], 16;" :: "r"(dst), "l"(src))
#define CP_COMMIT() asm volatile("cp.async.commit_group;" ::: "memory")
#define CP_WAIT(n)  asm volatile("cp.async.wait_group %0;" :: "n"(n) : "memory")

// mma.sync m16n8k16 bf16 (row.col): D += A*B
__device__ __forceinline__ void mma16(float* c, uint32_t a0, uint32_t a1,
                                      uint32_t a2, uint32_t a3, uint32_t b0, uint32_t b1) {
    asm volatile(
        "mma.sync.aligned.m16n8k16.row.col.f32.bf16.bf16.f32 "
        "{%0,%1,%2,%3}, {%4,%5,%6,%7}, {%8,%9}, {%0,%1,%2,%3};\n"
        : "+f"(c[0]), "+f"(c[1]), "+f"(c[2]), "+f"(c[3])
        : "r"(a0), "r"(a1), "r"(a2), "r"(a3), "r"(b0), "r"(b1));
}
__device__ __forceinline__ uint32_t pack_bf2(float x, float y) {
    __nv_bfloat162 h = __float22bfloat162_rn(make_float2(x, y));
    return *(uint32_t*)&h;
}

// ================= bf16 tensor-core GEMM (general, 3-stage pipeline) ==========
constexpr int BFBK = 64;
constexpr int BSTR = 36;                            // words per smem row (32+pad)
constexpr int BF_STAGE = 128 * BSTR * 4;            // 18432
constexpr int BF_SMEM = 6 * BF_STAGE;               // 110592

__device__ __forceinline__ void load_stage_bf(
    uint32_t smA, uint32_t smB,
    const __nv_bfloat16* __restrict__ Ab, const __nv_bfloat16* __restrict__ Bb,
    int K, int k0, int tid)
{
#pragma unroll
    for (int it = 0; it < 4; it++) {
        int idx = tid + it * 256;                    // 0..1023
        int row = idx >> 3, seg = idx & 7;
        CP16(smA + (uint32_t)(row * BSTR + seg * 4) * 4,
             Ab + (size_t)row * K + k0 + seg * 8);
    }
#pragma unroll
    for (int it = 0; it < 4; it++) {
        int idx = tid + it * 256;
        int row = idx >> 3, seg = idx & 7;
        CP16(smB + (uint32_t)(row * BSTR + seg * 4) * 4,
             Bb + (size_t)row * K + k0 + seg * 8);
    }
}

__global__ void __launch_bounds__(256) bf_gemm(
    const __nv_bfloat16* __restrict__ A, const __nv_bfloat16* __restrict__ B,
    void* __restrict__ C, int M, int N, int K, int Kloc, int kchunks,
    long long sA, long long sB, long long sC,
    float alpha, const float* __restrict__ bias, long long sBias, int relu,
    const float* __restrict__ rowscale, int atomic_out, int out_bf,
    const float* __restrict__ resid, float* __restrict__ stats_acc,
    void* __restrict__ C2, void* __restrict__ C3, int qkv)
{
    extern __shared__ char smem[];
    const int tid = threadIdx.x;
    const int wid = tid >> 5, lane = tid & 31;
    const int wm = wid & 3, wn = wid >> 2;
    const int g = lane >> 2, tg = lane & 3, t2 = tg << 1;
    const int bx = blockIdx.x, by = blockIdx.y;
    const int bz = blockIdx.z / kchunks;
    const int kc = blockIdx.z % kchunks;
    const int m0 = by * 128, n0 = bx * 128;
    const __nv_bfloat16* Ab = A + (size_t)bz * sA + (size_t)m0 * K + (size_t)kc * Kloc;
    const __nv_bfloat16* Bb = B + (size_t)bz * sB + (size_t)n0 * K + (size_t)kc * Kloc;

    const uint32_t sbase = smem_u32(smem);

    float acc[2][8][4];
#pragma unroll
    for (int i = 0; i < 2; i++)
#pragma unroll
        for (int j = 0; j < 8; j++)
#pragma unroll
            for (int v = 0; v < 4; v++) acc[i][j][v] = 0.f;

    const int KT = Kloc / BFBK;
    load_stage_bf(sbase, sbase + 3 * BF_STAGE, Ab, Bb, K, 0, tid);
    CP_COMMIT();
    if (KT > 1) {
        load_stage_bf(sbase + BF_STAGE, sbase + 4 * BF_STAGE, Ab, Bb, K, BFBK, tid);
        CP_COMMIT();
    }

    for (int kt = 0; kt < KT; kt++) {
        const int cur = kt % 3;
        if (kt + 1 < KT) { CP_WAIT(1); } else { CP_WAIT(0); }
        __syncthreads();
        if (kt + 2 < KT) {
            const int nxt = (kt + 2) % 3;
            load_stage_bf(sbase + nxt * BF_STAGE, sbase + (3 + nxt) * BF_STAGE,
                          Ab, Bb, K, (kt + 2) * BFBK, tid);
            CP_COMMIT();
        }

        const uint32_t* As = (const uint32_t*)(smem + (size_t)cur * BF_STAGE);
        const uint32_t* Bs = (const uint32_t*)(smem + (size_t)(3 + cur) * BF_STAGE);
#pragma unroll
        for (int step = 0; step < 4; step++) {
            const int kw = step * 8;
            uint32_t afr[2][4];
#pragma unroll
            for (int i = 0; i < 2; i++) {
                int r = wm * 32 + i * 16 + g;
                afr[i][0] = As[r * BSTR + kw + tg];
                afr[i][1] = As[(r + 8) * BSTR + kw + tg];
                afr[i][2] = As[r * BSTR + kw + tg + 4];
                afr[i][3] = As[(r + 8) * BSTR + kw + tg + 4];
            }
#pragma unroll
            for (int j = 0; j < 8; j++) {
                int n = wn * 64 + j * 8 + g;
                uint32_t b0 = Bs[n * BSTR + kw + tg];
                uint32_t b1 = Bs[n * BSTR + kw + tg + 4];
#pragma unroll
                for (int i = 0; i < 2; i++)
                    mma16(acc[i][j], afr[i][0], afr[i][1], afr[i][2], afr[i][3], b0, b1);
            }
        }
        __syncthreads();
    }

    const float* bp = bias ? bias + (size_t)bz * sBias : nullptr;
    const float* rs = rowscale ? rowscale + (size_t)bz * M : nullptr;
    const float* rp = resid ? resid + (size_t)bz * sC : nullptr;
    float lsum = 0.f, lss = 0.f;
#pragma unroll
    for (int i = 0; i < 2; i++) {
        int r = m0 + wm * 32 + i * 16 + g;
#pragma unroll
        for (int j = 0; j < 8; j++) {
            int c = n0 + wn * 64 + j * 8 + t2;
            float2 v0, v1;
            v0.x = acc[i][j][0] * alpha; v0.y = acc[i][j][1] * alpha;
            v1.x = acc[i][j][2] * alpha; v1.y = acc[i][j][3] * alpha;
            if (bp) {
                float bb0 = __ldg(bp + c), bb1 = __ldg(bp + c + 1);
                v0.x += bb0; v0.y += bb1;
                v1.x += bb0; v1.y += bb1;
            }
            if (relu) {
                v0.x = fmaxf(v0.x, 0.f); v0.y = fmaxf(v0.y, 0.f);
                v1.x = fmaxf(v1.x, 0.f); v1.y = fmaxf(v1.y, 0.f);
            }
            if (rs) {
                float s0 = rs[r], s1 = rs[r + 8];
                v0.x *= s0; v0.y *= s0;
                v1.x *= s1; v1.y *= s1;
            }
            if (rp) {
                v0.x += __ldg(rp + (size_t)r * N + c);
                v0.y += __ldg(rp + (size_t)r * N + c + 1);
                v1.x += __ldg(rp + (size_t)(r + 8) * N + c);
                v1.y += __ldg(rp + (size_t)(r + 8) * N + c + 1);
                lsum += v0.x + v0.y + v1.x + v1.y;
                lss  += v0.x * v0.x + v0.y * v0.y + v1.x * v1.x + v1.y * v1.y;
            }
            if (atomic_out) {
                float* Cb = (float*)C + (size_t)bz * sC;
                atomicAdd(Cb + (size_t)r * N + c,     v0.x);
                atomicAdd(Cb + (size_t)r * N + c + 1, v0.y);
                atomicAdd(Cb + (size_t)(r + 8) * N + c,     v1.x);
                atomicAdd(Cb + (size_t)(r + 8) * N + c + 1, v1.y);
            } else if (out_bf) {
                void* base = C;
                int Nout = N, cc = c;
                if (qkv) {
                    int sel = c >> 8;
                    base = (sel == 0) ? C : (sel == 1) ? C2 : C3;
                    Nout = 256;
                    cc = c & 255;
                }
                uint32_t* cb = (uint32_t*)((__nv_bfloat16*)base + (size_t)bz * sC);
                cb[((size_t)r * Nout + cc) >> 1]       = pack_bf2(v0.x, v0.y);
                cb[((size_t)(r + 8) * Nout + cc) >> 1] = pack_bf2(v1.x, v1.y);
            } else {
                float* Cb = (float*)C + (size_t)bz * sC;
                *(float2*)(Cb + (size_t)r * N + c)       = v0;
                *(float2*)(Cb + (size_t)(r + 8) * N + c) = v1;
            }
        }
    }
    if (stats_acc) {
        __shared__ float s_sum[256], s_ss[256];
        s_sum[tid] = lsum; s_ss[tid] = lss;
        __syncthreads();
        for (int o = 128; o; o >>= 1) {
            if (tid < o) { s_sum[tid] += s_sum[tid + o]; s_ss[tid] += s_ss[tid + o]; }
            __syncthreads();
        }
        if (tid == 0) {
            atomicAdd(&stats_acc[0], s_sum[0]);
            atomicAdd(&stats_acc[1], s_ss[0]);
        }
    }
}

// ---------------- batched fp32 -> bf16 conversions (one launch) ----------------
constexpr int CV_T0 = 4194304;                       // text
constexpr int CV_T1 = CV_T0 + 3 * 65536;             // Wq|Wk|Wv -> Wqkv
constexpr int CV_T2 = CV_T1 + 262144;                // W1
constexpr int CV_T3 = CV_T2 + 262144;                // W2 (total 4915200)

__global__ void convert_all(
    const float* __restrict__ text, const float* __restrict__ Wq,
    const float* __restrict__ Wk, const float* __restrict__ Wv,
    const float* __restrict__ W1, const float* __restrict__ W2,
    __nv_bfloat16* __restrict__ textbf, __nv_bfloat16* __restrict__ Wqkvbf,
    __nv_bfloat16* __restrict__ W1bf, __nv_bfloat16* __restrict__ W2bf)
{
    int i = blockIdx.x * 256 + threadIdx.x;
    if (i < CV_T0) {
        textbf[i] = __float2bfloat16(text[i]);
    } else if (i < CV_T1) {
        int j = i - CV_T0;
        const float* src = (j < 65536) ? Wq : (j < 131072) ? Wk : Wv;
        Wqkvbf[j] = __float2bfloat16(src[j & 65535]);
    } else if (i < CV_T2) {
        W1bf[i - CV_T1] = __float2bfloat16(W1[i - CV_T1]);
    } else if (i < CV_T3) {
        W2bf[i - CV_T2] = __float2bfloat16(W2[i - CV_T2]);
    }
}

__global__ void f2bf(const float* __restrict__ src, __nv_bfloat16* __restrict__ dst, int n) {
    int i = blockIdx.x * 256 + threadIdx.x;
    if (i < n) dst[i] = __float2bfloat16(src[i]);
}

// zero G2 + stats accumulators + build concatenated qkv bias (one launch)
__global__ void zero_all(float* __restrict__ G2, float* __restrict__ sacc,
                         const float* __restrict__ bq, const float* __restrict__ bk,
                         const float* __restrict__ bv, float* __restrict__ bqkv, int nG2) {
    int i = blockIdx.x * 256 + threadIdx.x;
    if (i < nG2) G2[i] = 0.f;
    if (i < 4) sacc[i] = 0.f;
    if (i < 3 * DIM) {
        const float* src = (i < DIM) ? bq : (i < 2 * DIM) ? bk : bv;
        bqkv[i] = src[i & (DIM - 1)];
    }
}

// ---------------- combined bf16 transpose (V and SK in one launch) ----------
__global__ void transpose2_bf(const __nv_bfloat16* __restrict__ V,
                              __nv_bfloat16* __restrict__ Vt,
                              const __nv_bfloat16* __restrict__ SK,
                              __nv_bfloat16* __restrict__ SKt) {
    __shared__ __nv_bfloat16 t[32][34];
    int zb = blockIdx.z;
    int b = zb & 3;
    const __nv_bfloat16* X = (zb < 4) ? V : SK;
    __nv_bfloat16* Xt = (zb < 4) ? Vt : SKt;
    int s0 = blockIdx.x * 32, d0 = blockIdx.y * 32;
    const __nv_bfloat16* Xb = X + (size_t)b * SEQ * DIM;
    __nv_bfloat16* Xtb = Xt + (size_t)b * SEQ * DIM;
    int x = threadIdx.x, y = threadIdx.y;
#pragma unroll
    for (int i = 0; i < 32; i += 8)
        t[y + i][x] = Xb[(size_t)(s0 + y + i) * DIM + d0 + x];
    __syncthreads();
#pragma unroll
    for (int i = 0; i < 32; i += 8)
        Xtb[(size_t)(d0 + y + i) * SEQ + s0 + x] = t[x][y + i];
}

// ---------------- combined column sums: Vsum and sksum partials ---------------
__global__ void colsum2_partial(const __nv_bfloat16* __restrict__ V,
                                const __nv_bfloat16* __restrict__ SK,
                                float* __restrict__ vpp, float* __restrict__ spp) {
    int ch = blockIdx.x, b = blockIdx.y, d = threadIdx.x;
    const __nv_bfloat16* Vb = V + (size_t)b * SEQ * DIM;
    const __nv_bfloat16* Sb = SK + (size_t)b * SEQ * DIM;
    float sv = 0.f, ss = 0.f;
    for (int s = ch * 128; s < ch * 128 + 128; s++) {
        sv += __bfloat162float(Vb[(size_t)s * DIM + d]);
        ss += __bfloat162float(Sb[(size_t)s * DIM + d]);
    }
    vpp[((size_t)b * 32 + ch) * DIM + d] = sv;
    spp[((size_t)b * 32 + ch) * DIM + d] = ss;
}
__global__ void colsum2_combine(const float* __restrict__ vpp, const float* __restrict__ spp,
                                float* __restrict__ Vsum, float* __restrict__ sksum) {
    int b = blockIdx.x, d = threadIdx.x;
    float sv = 0.f, ss = 0.f;
    for (int ch = 0; ch < 32; ch++) {
        sv += vpp[((size_t)b * 32 + ch) * DIM + d];
        ss += spp[((size_t)b * 32 + ch) * DIM + d];
    }
    Vsum[b * DIM + d] = sv;
    sksum[b * DIM + d] = ss;
}

// ---------------- rowscale = 1/(SEQ + q.sksum/16), q in bf16 ---------
__global__ void rowdiv_kernel(const __nv_bfloat16* __restrict__ Q,
                              const float* __restrict__ sksum,
                              float* __restrict__ rowscale) {
    int wid = threadIdx.x >> 5, lane = threadIdx.x & 31;
    int row = blockIdx.x * 8 + wid;
    int b = row >> 12;
    const uint32_t* q = (const uint32_t*)(Q + (size_t)row * DIM);
    const float* sk = sksum + b * DIM;
    float s = 0.f;
#pragma unroll
    for (int k = 0; k < 4; k++) {
        int w = lane + k * 32;
        __nv_bfloat162 h = *(const __nv_bfloat162*)&q[w];
        s += __bfloat162float(h.x) * sk[2 * w] + __bfloat162float(h.y) * sk[2 * w + 1];
    }
#pragma unroll
    for (int o = 16; o; o >>= 1) s += __shfl_xor_sync(0xffffffffu, s, o);
    if (lane == 0) rowscale[row] = 1.f / ((float)SEQ + s * 0.0625f);
}

// ---------------- prefix sums of K rows (bf16 K, analytic sparse@K) ----------
__global__ void prefix_partial(const __nv_bfloat16* __restrict__ Kmat, float* __restrict__ pp) {
    int ch = blockIdx.x, b = blockIdx.y, d = threadIdx.x;
    int s0 = ch * 128;
    int s1 = min(s0 + 128, 2047);
    const __nv_bfloat16* Kb = Kmat + (size_t)b * SEQ * DIM;
    float s = 0.f;
    for (int ss = s0; ss < s1; ss++) s += __bfloat162float(Kb[(size_t)ss * DIM + d]);
    pp[((size_t)b * 16 + ch) * DIM + d] = s;
}

__global__ void prefix_combine(const __nv_bfloat16* __restrict__ Kmat,
                               const float* __restrict__ pp, float* __restrict__ P) {
    int b = blockIdx.x, d = threadIdx.x;
    const __nv_bfloat16* Kb = Kmat + (size_t)b * SEQ * DIM;
    float s = 0.f;
    for (int ch = 0; ch < 16; ch++) s += pp[((size_t)b * 16 + ch) * DIM + d];
    float p2047 = s;
    float p2048 = p2047 + __bfloat162float(Kb[(size_t)2047 * DIM + d]);
    float p2049 = p2048 + __bfloat162float(Kb[(size_t)2048 * DIM + d]);
    float p2052 = p2049 + __bfloat162float(Kb[(size_t)2049 * DIM + d])
                        + __bfloat162float(Kb[(size_t)2050 * DIM + d])
                        + __bfloat162float(Kb[(size_t)2051 * DIM + d]);
    float* Pb = P + (size_t)b * 4 * DIM;
    Pb[0 * DIM + d] = p2047;
    Pb[1 * DIM + d] = p2048;
    Pb[2 * DIM + d] = p2049;
    Pb[3 * DIM + d] = p2052;
}

__global__ void sk_kernel(const __nv_bfloat16* __restrict__ Kmat, const float* __restrict__ P,
                          __nv_bfloat16* __restrict__ SK,
                          float A3, float B3, float A4, float B4, float A5, float B5) {
    int i = blockIdx.x, b = blockIdx.y, d = threadIdx.x;
    const __nv_bfloat16* Kb = Kmat + (size_t)b * SEQ * DIM;
    int lo = max(i - 2, 0), hi = min(i + 2, SEQ - 1);
    int n = hi - lo + 1;
    float band = 0.f;
    for (int j = lo; j <= hi; j++) band += __bfloat162float(Kb[(size_t)j * DIM + d]);
    const float* Pb = P + (size_t)b * 4 * DIM;
    float off;
    if (i <= 2048) off = Pb[3 * DIM + d] - band;
    else           off = Pb[(5 - n) * DIM + d];
    float a, bb;
    if (n == 5)      { a = A5; bb = B5; }
    else if (n == 4) { a = A4; bb = B4; }
    else             { a = A3; bb = B3; }
    SK[((size_t)b * SEQ + i) * DIM + d] = __float2bfloat16(a * band + bb * off);
}

// ---------------- LN finalize (stats from fused accumulators) ----------------
__global__ void ln_combine2(const float* __restrict__ sacc, float* __restrict__ stats, int which) {
    double n = (double)TXT_N;
    double mu = (double)sacc[which * 2] / n;
    double var = (double)sacc[which * 2 + 1] / n - mu * mu;
    stats[which * 2]     = (float)mu;
    stats[which * 2 + 1] = (float)(1.0 / sqrt(var + 1e-6));
}

__global__ void ln_apply1_bf(const float* __restrict__ x,
                             const float* __restrict__ g, const float* __restrict__ bta,
                             const float* __restrict__ stats, int which,
                             __nv_bfloat16* __restrict__ out) {
    size_t i = (size_t)blockIdx.x * 256 + threadIdx.x;
    float mu = stats[which * 2], r = stats[which * 2 + 1];
    out[i] = __float2bfloat16((x[i] - mu) * r * g[i] + bta[i]);
}

// final LN apply + image passthrough in one launch
__global__ void ln_apply_final(const float* __restrict__ x,
                               const float* __restrict__ g, const float* __restrict__ bta,
                               const float* __restrict__ stats, int which,
                               float* __restrict__ out,
                               const float* __restrict__ image, float* __restrict__ img_out,
                               int img_n) {
    size_t i = (size_t)blockIdx.x * 256 + threadIdx.x;
    if (i < TXT_N) {
        float mu = stats[which * 2], r = stats[which * 2 + 1];
        out[i] = (x[i] - mu) * r * g[i] + bta[i];
    } else {
        size_t j = i - TXT_N;
        if (j < (size_t)img_n) img_out[j] = image[j];
    }
}

// ---------------- launch ----------------
extern "C" void kernel_launch(void* const* d_in, const int* in_sizes, int n_in,
                              void* d_out, int out_size) {
    const float* text  = (const float*)d_in[0];
    const float* image = (const float*)d_in[1];
    const float* Wq = (const float*)d_in[2];
    const float* bq = (const float*)d_in[3];
    const float* Wk = (const float*)d_in[4];
    const float* bk = (const float*)d_in[5];
    const float* Wv = (const float*)d_in[6];
    const float* bv = (const float*)d_in[7];
    const float* W1 = (const float*)d_in[8];
    const float* b1 = (const float*)d_in[9];
    const float* W2 = (const float*)d_in[10];
    const float* b2 = (const float*)d_in[11];
    const float* gamma = (const float*)d_in[12];
    const float* beta  = (const float*)d_in[13];
    float* out = (float*)d_out;

    float *Osum, *M2sum, *G2, *sacc, *stats, *P, *pp, *vpp, *spp, *Vsum, *sksum, *rowscale, *bqkv;
    __nv_bfloat16 *textbf, *Qbf, *Kbf, *Vbf, *Vtbf, *SKbf, *SKtbf, *Hbf, *FFbf;
    __nv_bfloat16 *Wqkvbf, *W1bf, *W2bf, *G2bf;
    cudaGetSymbolAddress((void**)&textbf, g_textbf);
    cudaGetSymbolAddress((void**)&Qbf,  g_Qbf);
    cudaGetSymbolAddress((void**)&Kbf,  g_Kbf);
    cudaGetSymbolAddress((void**)&Vbf,  g_Vbf);
    cudaGetSymbolAddress((void**)&Vtbf, g_Vtbf);
    cudaGetSymbolAddress((void**)&SKbf, g_SKbf);
    cudaGetSymbolAddress((void**)&SKtbf, g_SKtbf);
    cudaGetSymbolAddress((void**)&Hbf,  g_Hbf);
    cudaGetSymbolAddress((void**)&FFbf, g_FFbf);
    cudaGetSymbolAddress((void**)&Wqkvbf, g_Wqkvbf);
    cudaGetSymbolAddress((void**)&W1bf, g_W1bf);
    cudaGetSymbolAddress((void**)&W2bf, g_W2bf);
    cudaGetSymbolAddress((void**)&G2bf, g_G2bf);
    cudaGetSymbolAddress((void**)&bqkv, g_bqkv);
    cudaGetSymbolAddress((void**)&Osum, g_Osum);
    cudaGetSymbolAddress((void**)&M2sum, g_M2sum);
    cudaGetSymbolAddress((void**)&G2,  g_G2);
    cudaGetSymbolAddress((void**)&sacc, g_sacc);
    cudaGetSymbolAddress((void**)&stats, g_stats);
    cudaGetSymbolAddress((void**)&P,   g_P);
    cudaGetSymbolAddress((void**)&pp,  g_pp);
    cudaGetSymbolAddress((void**)&vpp, g_vpp);
    cudaGetSymbolAddress((void**)&spp, g_spp);
    cudaGetSymbolAddress((void**)&Vsum, g_Vsum);
    cudaGetSymbolAddress((void**)&sksum, g_sksum);
    cudaGetSymbolAddress((void**)&rowscale, g_rowscale);

    static int smem_set = 0;
    if (!smem_set) {
        cudaFuncSetAttribute(bf_gemm, cudaFuncAttributeMaxDynamicSharedMemorySize, BF_SMEM);
        smem_set = 1;
    }

    // sparse-softmax coefficients
    double e = exp(1.0);
    float A[6], Bc[6];
    for (int n = 3; n <= 5; n++) {
        double Z = n * e + (double)(SEQ - n);
        A[n]  = (float)(e / Z);
        Bc[n] = (float)(1.0 / Z);
    }

    // conversions to bf16 (one launch) + zero/bias-concat (one launch)
    convert_all<<<CV_T3 / 256, 256>>>(text, Wq, Wk, Wv, W1, W2,
                                      textbf, Wqkvbf, W1bf, W2bf);
    zero_all<<<(BATCH * DIM * DIM + 255) / 256, 256>>>(G2, sacc, bq, bk, bv, bqkv,
                                                       BATCH * DIM * DIM);

    // fused QKV projection: [16384, 768] routed into Qbf/Kbf/Vbf
    bf_gemm<<<dim3(6, 128, 1), 256, BF_SMEM>>>(textbf, Wqkvbf, Qbf,
        NTOK, 3 * DIM, DIM, DIM, 1, 0, 0, 0,
        1.f, bqkv, 0, 0, nullptr, 0, 1, nullptr, nullptr, Kbf, Vbf, 1);

    // analytic sparse @ K -> SKbf
    prefix_partial<<<dim3(16, BATCH), 256>>>(Kbf, pp);
    prefix_combine<<<BATCH, 256>>>(Kbf, pp, P);
    sk_kernel<<<dim3(SEQ, BATCH), 256>>>(Kbf, P, SKbf, A[3], Bc[3], A[4], Bc[4], A[5], Bc[5]);

    // combined transposes (V, SK) and column sums (Vsum, sksum)
    transpose2_bf<<<dim3(128, 8, 8), dim3(32, 8)>>>(Vbf, Vtbf, SKbf, SKtbf);
    colsum2_partial<<<dim3(32, BATCH), 256>>>(Vbf, SKbf, vpp, spp);
    colsum2_combine<<<BATCH, 256>>>(vpp, spp, Vsum, sksum);

    // rowscale = 1/(SEQ + q.sksum/16)
    rowdiv_kernel<<<NTOK / 8, 256>>>(Qbf, sksum, rowscale);

    // G2[b,e,d] = sum_j V[j,e] SK[j,d]  (split-K=16, atomic fp32), then bf16
    bf_gemm<<<dim3(2, 2, BATCH * 16), 256, BF_SMEM>>>(Vtbf, SKtbf, G2,
        DIM, DIM, SEQ, SEQ / 16, 16,
        (long long)DIM * SEQ, (long long)DIM * SEQ, (long long)DIM * DIM,
        1.f, nullptr, 0, 0, nullptr, 1, 0, nullptr, nullptr, nullptr, nullptr, 0);
    f2bf<<<(BATCH * DIM * DIM + 255) / 256, 256>>>(G2, G2bf, BATCH * DIM * DIM);

    // Osum = (Vsum + Q@G2^T/16)*rowscale + text, with fused LN1 stats
    bf_gemm<<<dim3(2, 32, BATCH), 256, BF_SMEM>>>(Qbf, G2bf, Osum,
        SEQ, DIM, DIM, DIM, 1,
        (long long)SEQ * DIM, (long long)DIM * DIM, (long long)SEQ * DIM,
        0.0625f, Vsum, DIM, 0, rowscale, 0, 0, text, &sacc[0], nullptr, nullptr, 0);

    // LN1 finalize -> Hbf
    ln_combine2<<<1, 1>>>(sacc, stats, 0);
    ln_apply1_bf<<<NTOK, 256>>>(Osum, gamma, beta, stats, 0, Hbf);

    // MLP (bf16 operands, fp32 accumulate); MLP2 fuses +text and LN2 stats
    bf_gemm<<<dim3(8, 128, 1), 256, BF_SMEM>>>(Hbf, W1bf, FFbf, NTOK, DFF, DIM, DIM, 1,
        0, 0, 0, 1.f, b1, 0, 1, nullptr, 0, 1, nullptr, nullptr, nullptr, nullptr, 0);
    bf_gemm<<<dim3(2, 128, 1), 256, BF_SMEM>>>(FFbf, W2bf, M2sum, NTOK, DIM, DFF, DFF, 1,
        0, 0, 0, 1.f, b2, 0, 0, nullptr, 0, 0, text, &sacc[2], nullptr, nullptr, 0);

    // LN2 finalize -> out, with image passthrough fused
    ln_combine2<<<1, 1>>>(sacc, stats, 1);
    int img_n = (out_size >= (int)TXT_N + IMG_N) ? IMG_N : 0;
    ln_apply_final<<<NTOK + (IMG_N + 255) / 256, 256>>>(M2sum, gamma, beta, stats, 1,
                                                        out, image, out + TXT_N, img_n);
}

// round 15
// speedup vs baseline: 1.0616x; 1.0606x over previous
#include <cuda_runtime.h>
#include <cuda_bf16.h>
#include <math.h>
#include <stdint.h>

// ---------------- problem constants ----------------
constexpr int BATCH = 4;
constexpr int SEQ   = 4096;
constexpr int DIM   = 256;
constexpr int DFF   = 1024;
constexpr int NTOK  = BATCH * SEQ;                 // 16384
constexpr size_t TXT_N = (size_t)NTOK * DIM;       // 4,194,304
constexpr int IMG_N = BATCH * 196 * DIM;           // 200,704

// ---------------- scratch (device globals; no allocs allowed) ----------------
__device__ __align__(16) __nv_bfloat16 g_textbf[4194304];
__device__ __align__(16) __nv_bfloat16 g_Qbf [4194304];
__device__ __align__(16) __nv_bfloat16 g_Kbf [4194304];
__device__ __align__(16) __nv_bfloat16 g_Vbf [4194304];
__device__ __align__(16) __nv_bfloat16 g_Vtbf[4194304];
__device__ __align__(16) __nv_bfloat16 g_SKbf[4194304];
__device__ __align__(16) __nv_bfloat16 g_SKtbf[4194304];
__device__ __align__(16) __nv_bfloat16 g_Hbf [4194304];
__device__ __align__(16) __nv_bfloat16 g_FFbf[16777216];
__device__ __align__(16) __nv_bfloat16 g_Wqkvbf[3 * DIM * DIM];   // [768, 256]
__device__ __align__(16) __nv_bfloat16 g_W1bf[DFF * DIM];
__device__ __align__(16) __nv_bfloat16 g_W2bf[DIM * DFF];
__device__ __align__(16) __nv_bfloat16 g_G2bf[BATCH * DIM * DIM];
__device__ float g_bqkv[3 * DIM];
__device__ float g_Osum [4194304];                 // attn + text (fp32)
__device__ float g_M2sum[4194304];                 // mlp + text (fp32)
__device__ float g_G2 [BATCH * DIM * DIM];
__device__ float g_sacc[4];                        // [sum1, ss1, sum2, ss2]
__device__ float g_stats[4];                       // [mu1, r1, mu2, r2]
__device__ float g_P [BATCH * 4 * DIM];
__device__ float g_pp[BATCH * 64 * DIM];
__device__ float g_vpp[BATCH * 32 * DIM];
__device__ float g_spp[BATCH * 32 * DIM];
__device__ float g_Vsum[BATCH * DIM];
__device__ float g_sksum[BATCH * DIM];
__device__ float g_rowscale[NTOK];

// ================= helpers =================
__device__ __forceinline__ uint32_t smem_u32(const void* p) {
    uint32_t a;
    asm("{ .reg .u64 t; cvta.to.shared.u64 t, %1; cvt.u32.u64 %0, t; }" : "=r"(a) : "l"(p));
    return a;
}
#define CP16(dst, src) \
    asm volatile("cp.async.cg.shared.global [%0], [%1], 16;" :: "r"(dst), "l"(src))
#define CP_COMMIT() asm volatile("cp.async.commit_group;" ::: "memory")
#define CP_WAIT(n)  asm volatile("cp.async.wait_group %0;" :: "n"(n) : "memory")
#define LDSM_X4(r, addr) \
    asm volatile("ldmatrix.sync.aligned.m8n8.x4.shared.b16 {%0,%1,%2,%3}, [%4];" \
        : "=r"((r)[0]), "=r"((r)[1]), "=r"((r)[2]), "=r"((r)[3]) : "r"(addr))

// mma.sync m16n8k16 bf16 (row.col): D += A*B
__device__ __forceinline__ void mma16(float* c, uint32_t a0, uint32_t a1,
                                      uint32_t a2, uint32_t a3, uint32_t b0, uint32_t b1) {
    asm volatile(
        "mma.sync.aligned.m16n8k16.row.col.f32.bf16.bf16.f32 "
        "{%0,%1,%2,%3}, {%4,%5,%6,%7}, {%8,%9}, {%0,%1,%2,%3};\n"
        : "+f"(c[0]), "+f"(c[1]), "+f"(c[2]), "+f"(c[3])
        : "r"(a0), "r"(a1), "r"(a2), "r"(a3), "r"(b0), "r"(b1));
}
__device__ __forceinline__ uint32_t pack_bf2(float x, float y) {
    __nv_bfloat162 h = __float22bfloat162_rn(make_float2(x, y));
    return *(uint32_t*)&h;
}

// ================= bf16 tensor-core GEMM (2-stage, ldmatrix operands) =========
constexpr int BFBK = 64;
constexpr int BSTR = 36;                            // words per smem row (32+pad)
constexpr int BF_STAGE = 128 * BSTR * 4;            // 18432
constexpr int BF_SMEM = 4 * BF_STAGE;               // 73728 -> 2 CTAs/SM

__device__ __forceinline__ void load_stage_bf(
    uint32_t smA, uint32_t smB,
    const __nv_bfloat16* __restrict__ Ab, const __nv_bfloat16* __restrict__ Bb,
    int K, int k0, int tid)
{
#pragma unroll
    for (int it = 0; it < 4; it++) {
        int idx = tid + it * 256;                    // 0..1023
        int row = idx >> 3, seg = idx & 7;
        CP16(smA + (uint32_t)(row * BSTR + seg * 4) * 4,
             Ab + (size_t)row * K + k0 + seg * 8);
    }
#pragma unroll
    for (int it = 0; it < 4; it++) {
        int idx = tid + it * 256;
        int row = idx >> 3, seg = idx & 7;
        CP16(smB + (uint32_t)(row * BSTR + seg * 4) * 4,
             Bb + (size_t)row * K + k0 + seg * 8);
    }
}

__global__ void __launch_bounds__(256) bf_gemm(
    const __nv_bfloat16* __restrict__ A, const __nv_bfloat16* __restrict__ B,
    void* __restrict__ C, int M, int N, int K, int Kloc, int kchunks,
    long long sA, long long sB, long long sC,
    float alpha, const float* __restrict__ bias, long long sBias, int relu,
    const float* __restrict__ rowscale, int atomic_out, int out_bf,
    const float* __restrict__ resid, float* __restrict__ stats_acc,
    void* __restrict__ C2, void* __restrict__ C3, int qkv)
{
    extern __shared__ char smem[];
    const int tid = threadIdx.x;
    const int wid = tid >> 5, lane = tid & 31;
    const int wm = wid & 3, wn = wid >> 2;
    const int g = lane >> 2, tg = lane & 3, t2 = tg << 1;
    const int bx = blockIdx.x, by = blockIdx.y;
    const int bz = blockIdx.z / kchunks;
    const int kc = blockIdx.z % kchunks;
    const int m0 = by * 128, n0 = bx * 128;
    const __nv_bfloat16* Ab = A + (size_t)bz * sA + (size_t)m0 * K + (size_t)kc * Kloc;
    const __nv_bfloat16* Bb = B + (size_t)bz * sB + (size_t)n0 * K + (size_t)kc * Kloc;

    const uint32_t sbase = smem_u32(smem);
    // ldmatrix per-thread byte offsets (relative to stage base)
    const int lrow8  = lane & 7;
    const int a_row  = lrow8 + ((lane >> 3) & 1) * 8;   // within 16-row A tile
    const int a_colw = ((lane >> 4) & 1) * 4;           // 0 or 4 words (k or k+8)
    uint32_t a_off[2];
#pragma unroll
    for (int i = 0; i < 2; i++)
        a_off[i] = (uint32_t)((wm * 32 + i * 16 + a_row) * BSTR + a_colw) * 4;
    const int b_row  = lrow8 + ((lane >> 4) & 1) * 8;   // within 16-row B pair
    const int b_colw = ((lane >> 3) & 1) * 4;
    uint32_t b_off[4];
#pragma unroll
    for (int p = 0; p < 4; p++)
        b_off[p] = (uint32_t)((wn * 64 + p * 16 + b_row) * BSTR + b_colw) * 4;

    float acc[2][8][4];
#pragma unroll
    for (int i = 0; i < 2; i++)
#pragma unroll
        for (int j = 0; j < 8; j++)
#pragma unroll
            for (int v = 0; v < 4; v++) acc[i][j][v] = 0.f;

    const int KT = Kloc / BFBK;
    load_stage_bf(sbase, sbase + 2 * BF_STAGE, Ab, Bb, K, 0, tid);
    CP_COMMIT();

    for (int kt = 0; kt < KT; kt++) {
        const int cur = kt & 1;
        if (kt + 1 < KT) {
            load_stage_bf(sbase + (cur ^ 1) * BF_STAGE, sbase + (2 + (cur ^ 1)) * BF_STAGE,
                          Ab, Bb, K, (kt + 1) * BFBK, tid);
            CP_COMMIT();
            CP_WAIT(1);
        } else {
            CP_WAIT(0);
        }
        __syncthreads();

        const uint32_t aBase = sbase + (uint32_t)cur * BF_STAGE;
        const uint32_t bBase = sbase + (uint32_t)(2 + cur) * BF_STAGE;
#pragma unroll
        for (int step = 0; step < 4; step++) {
            const uint32_t so = (uint32_t)step * 32;   // 8 words = 32 bytes
            uint32_t afr[2][4];
            LDSM_X4(afr[0], aBase + a_off[0] + so);
            LDSM_X4(afr[1], aBase + a_off[1] + so);
            uint32_t bfr[4][4];
#pragma unroll
            for (int p = 0; p < 4; p++)
                LDSM_X4(bfr[p], bBase + b_off[p] + so);
#pragma unroll
            for (int p = 0; p < 4; p++) {
#pragma unroll
                for (int i = 0; i < 2; i++) {
                    mma16(acc[i][2 * p],     afr[i][0], afr[i][1], afr[i][2], afr[i][3],
                          bfr[p][0], bfr[p][1]);
                    mma16(acc[i][2 * p + 1], afr[i][0], afr[i][1], afr[i][2], afr[i][3],
                          bfr[p][2], bfr[p][3]);
                }
            }
        }
        __syncthreads();
    }

    const float* bp = bias ? bias + (size_t)bz * sBias : nullptr;
    const float* rs = rowscale ? rowscale + (size_t)bz * M : nullptr;
    const float* rp = resid ? resid + (size_t)bz * sC : nullptr;
    float lsum = 0.f, lss = 0.f;
#pragma unroll
    for (int i = 0; i < 2; i++) {
        int r = m0 + wm * 32 + i * 16 + g;
#pragma unroll
        for (int j = 0; j < 8; j++) {
            int c = n0 + wn * 64 + j * 8 + t2;
            float2 v0, v1;
            v0.x = acc[i][j][0] * alpha; v0.y = acc[i][j][1] * alpha;
            v1.x = acc[i][j][2] * alpha; v1.y = acc[i][j][3] * alpha;
            if (bp) {
                float bb0 = __ldg(bp + c), bb1 = __ldg(bp + c + 1);
                v0.x += bb0; v0.y += bb1;
                v1.x += bb0; v1.y += bb1;
            }
            if (relu) {
                v0.x = fmaxf(v0.x, 0.f); v0.y = fmaxf(v0.y, 0.f);
                v1.x = fmaxf(v1.x, 0.f); v1.y = fmaxf(v1.y, 0.f);
            }
            if (rs) {
                float s0 = rs[r], s1 = rs[r + 8];
                v0.x *= s0; v0.y *= s0;
                v1.x *= s1; v1.y *= s1;
            }
            if (rp) {
                v0.x += __ldg(rp + (size_t)r * N + c);
                v0.y += __ldg(rp + (size_t)r * N + c + 1);
                v1.x += __ldg(rp + (size_t)(r + 8) * N + c);
                v1.y += __ldg(rp + (size_t)(r + 8) * N + c + 1);
                lsum += v0.x + v0.y + v1.x + v1.y;
                lss  += v0.x * v0.x + v0.y * v0.y + v1.x * v1.x + v1.y * v1.y;
            }
            if (atomic_out) {
                float* Cb = (float*)C + (size_t)bz * sC;
                atomicAdd(Cb + (size_t)r * N + c,     v0.x);
                atomicAdd(Cb + (size_t)r * N + c + 1, v0.y);
                atomicAdd(Cb + (size_t)(r + 8) * N + c,     v1.x);
                atomicAdd(Cb + (size_t)(r + 8) * N + c + 1, v1.y);
            } else if (out_bf) {
                void* base = C;
                int Nout = N, cc = c;
                if (qkv) {
                    int sel = c >> 8;
                    base = (sel == 0) ? C : (sel == 1) ? C2 : C3;
                    Nout = 256;
                    cc = c & 255;
                }
                uint32_t* cb = (uint32_t*)((__nv_bfloat16*)base + (size_t)bz * sC);
                cb[((size_t)r * Nout + cc) >> 1]       = pack_bf2(v0.x, v0.y);
                cb[((size_t)(r + 8) * Nout + cc) >> 1] = pack_bf2(v1.x, v1.y);
            } else {
                float* Cb = (float*)C + (size_t)bz * sC;
                *(float2*)(Cb + (size_t)r * N + c)       = v0;
                *(float2*)(Cb + (size_t)(r + 8) * N + c) = v1;
            }
        }
    }
    if (stats_acc) {
        __shared__ float s_sum[256], s_ss[256];
        s_sum[tid] = lsum; s_ss[tid] = lss;
        __syncthreads();
        for (int o = 128; o; o >>= 1) {
            if (tid < o) { s_sum[tid] += s_sum[tid + o]; s_ss[tid] += s_ss[tid + o]; }
            __syncthreads();
        }
        if (tid == 0) {
            atomicAdd(&stats_acc[0], s_sum[0]);
            atomicAdd(&stats_acc[1], s_ss[0]);
        }
    }
}

// ---------------- batched fp32 -> bf16 conversions (one launch) ----------------
constexpr int CV_T0 = 4194304;                       // text
constexpr int CV_T1 = CV_T0 + 3 * 65536;             // Wq|Wk|Wv -> Wqkv
constexpr int CV_T2 = CV_T1 + 262144;                // W1
constexpr int CV_T3 = CV_T2 + 262144;                // W2 (total 4915200)

__global__ void convert_all(
    const float* __restrict__ text, const float* __restrict__ Wq,
    const float* __restrict__ Wk, const float* __restrict__ Wv,
    const float* __restrict__ W1, const float* __restrict__ W2,
    __nv_bfloat16* __restrict__ textbf, __nv_bfloat16* __restrict__ Wqkvbf,
    __nv_bfloat16* __restrict__ W1bf, __nv_bfloat16* __restrict__ W2bf)
{
    int i = blockIdx.x * 256 + threadIdx.x;
    if (i < CV_T0) {
        textbf[i] = __float2bfloat16(text[i]);
    } else if (i < CV_T1) {
        int j = i - CV_T0;
        const float* src = (j < 65536) ? Wq : (j < 131072) ? Wk : Wv;
        Wqkvbf[j] = __float2bfloat16(src[j & 65535]);
    } else if (i < CV_T2) {
        W1bf[i - CV_T1] = __float2bfloat16(W1[i - CV_T1]);
    } else if (i < CV_T3) {
        W2bf[i - CV_T2] = __float2bfloat16(W2[i - CV_T2]);
    }
}

__global__ void f2bf(const float* __restrict__ src, __nv_bfloat16* __restrict__ dst, int n) {
    int i = blockIdx.x * 256 + threadIdx.x;
    if (i < n) dst[i] = __float2bfloat16(src[i]);
}

// zero G2 + stats accumulators + build concatenated qkv bias (one launch)
__global__ void zero_all(float* __restrict__ G2, float* __restrict__ sacc,
                         const float* __restrict__ bq, const float* __restrict__ bk,
                         const float* __restrict__ bv, float* __restrict__ bqkv, int nG2) {
    int i = blockIdx.x * 256 + threadIdx.x;
    if (i < nG2) G2[i] = 0.f;
    if (i < 4) sacc[i] = 0.f;
    if (i < 3 * DIM) {
        const float* src = (i < DIM) ? bq : (i < 2 * DIM) ? bk : bv;
        bqkv[i] = src[i & (DIM - 1)];
    }
}

// ---------------- combined bf16 transpose (V and SK in one launch) ----------
__global__ void transpose2_bf(const __nv_bfloat16* __restrict__ V,
                              __nv_bfloat16* __restrict__ Vt,
                              const __nv_bfloat16* __restrict__ SK,
                              __nv_bfloat16* __restrict__ SKt) {
    __shared__ __nv_bfloat16 t[32][34];
    int zb = blockIdx.z;
    int b = zb & 3;
    const __nv_bfloat16* X = (zb < 4) ? V : SK;
    __nv_bfloat16* Xt = (zb < 4) ? Vt : SKt;
    int s0 = blockIdx.x * 32, d0 = blockIdx.y * 32;
    const __nv_bfloat16* Xb = X + (size_t)b * SEQ * DIM;
    __nv_bfloat16* Xtb = Xt + (size_t)b * SEQ * DIM;
    int x = threadIdx.x, y = threadIdx.y;
#pragma unroll
    for (int i = 0; i < 32; i += 8)
        t[y + i][x] = Xb[(size_t)(s0 + y + i) * DIM + d0 + x];
    __syncthreads();
#pragma unroll
    for (int i = 0; i < 32; i += 8)
        Xtb[(size_t)(d0 + y + i) * SEQ + s0 + x] = t[x][y + i];
}

// ---------------- combined column sums: Vsum and sksum partials ---------------
__global__ void colsum2_partial(const __nv_bfloat16* __restrict__ V,
                                const __nv_bfloat16* __restrict__ SK,
                                float* __restrict__ vpp, float* __restrict__ spp) {
    int ch = blockIdx.x, b = blockIdx.y, d = threadIdx.x;
    const __nv_bfloat16* Vb = V + (size_t)b * SEQ * DIM;
    const __nv_bfloat16* Sb = SK + (size_t)b * SEQ * DIM;
    float sv = 0.f, ss = 0.f;
    for (int s = ch * 128; s < ch * 128 + 128; s++) {
        sv += __bfloat162float(Vb[(size_t)s * DIM + d]);
        ss += __bfloat162float(Sb[(size_t)s * DIM + d]);
    }
    vpp[((size_t)b * 32 + ch) * DIM + d] = sv;
    spp[((size_t)b * 32 + ch) * DIM + d] = ss;
}
__global__ void colsum2_combine(const float* __restrict__ vpp, const float* __restrict__ spp,
                                float* __restrict__ Vsum, float* __restrict__ sksum) {
    int b = blockIdx.x, d = threadIdx.x;
    float sv = 0.f, ss = 0.f;
    for (int ch = 0; ch < 32; ch++) {
        sv += vpp[((size_t)b * 32 + ch) * DIM + d];
        ss += spp[((size_t)b * 32 + ch) * DIM + d];
    }
    Vsum[b * DIM + d] = sv;
    sksum[b * DIM + d] = ss;
}

// ---------------- rowscale = 1/(SEQ + q.sksum/16), q in bf16 ---------
__global__ void rowdiv_kernel(const __nv_bfloat16* __restrict__ Q,
                              const float* __restrict__ sksum,
                              float* __restrict__ rowscale) {
    int wid = threadIdx.x >> 5, lane = threadIdx.x & 31;
    int row = blockIdx.x * 8 + wid;
    int b = row >> 12;
    const uint32_t* q = (const uint32_t*)(Q + (size_t)row * DIM);
    const float* sk = sksum + b * DIM;
    float s = 0.f;
#pragma unroll
    for (int k = 0; k < 4; k++) {
        int w = lane + k * 32;
        __nv_bfloat162 h = *(const __nv_bfloat162*)&q[w];
        s += __bfloat162float(h.x) * sk[2 * w] + __bfloat162float(h.y) * sk[2 * w + 1];
    }
#pragma unroll
    for (int o = 16; o; o >>= 1) s += __shfl_xor_sync(0xffffffffu, s, o);
    if (lane == 0) rowscale[row] = 1.f / ((float)SEQ + s * 0.0625f);
}

// ---------------- prefix sums of K rows (bf16 K, analytic sparse@K) ----------
__global__ void prefix_partial(const __nv_bfloat16* __restrict__ Kmat, float* __restrict__ pp) {
    int ch = blockIdx.x, b = blockIdx.y, d = threadIdx.x;   // 64 chunks of 32 rows
    int s0 = ch * 32;
    int s1 = min(s0 + 32, 2047);
    const __nv_bfloat16* Kb = Kmat + (size_t)b * SEQ * DIM;
    float s = 0.f;
    for (int ss = s0; ss < s1; ss++) s += __bfloat162float(Kb[(size_t)ss * DIM + d]);
    pp[((size_t)b * 64 + ch) * DIM + d] = s;
}

__global__ void prefix_combine(const __nv_bfloat16* __restrict__ Kmat,
                               const float* __restrict__ pp, float* __restrict__ P) {
    int b = blockIdx.x, d = threadIdx.x;
    const __nv_bfloat16* Kb = Kmat + (size_t)b * SEQ * DIM;
    float s = 0.f;
    for (int ch = 0; ch < 64; ch++) s += pp[((size_t)b * 64 + ch) * DIM + d];
    float p2047 = s;
    float p2048 = p2047 + __bfloat162float(Kb[(size_t)2047 * DIM + d]);
    float p2049 = p2048 + __bfloat162float(Kb[(size_t)2048 * DIM + d]);
    float p2052 = p2049 + __bfloat162float(Kb[(size_t)2049 * DIM + d])
                        + __bfloat162float(Kb[(size_t)2050 * DIM + d])
                        + __bfloat162float(Kb[(size_t)2051 * DIM + d]);
    float* Pb = P + (size_t)b * 4 * DIM;
    Pb[0 * DIM + d] = p2047;
    Pb[1 * DIM + d] = p2048;
    Pb[2 * DIM + d] = p2049;
    Pb[3 * DIM + d] = p2052;
}

__global__ void sk_kernel(const __nv_bfloat16* __restrict__ Kmat, const float* __restrict__ P,
                          __nv_bfloat16* __restrict__ SK,
                          float A3, float B3, float A4, float B4, float A5, float B5) {
    int i = blockIdx.x, b = blockIdx.y, d = threadIdx.x;
    const __nv_bfloat16* Kb = Kmat + (size_t)b * SEQ * DIM;
    int lo = max(i - 2, 0), hi = min(i + 2, SEQ - 1);
    int n = hi - lo + 1;
    float band = 0.f;
    for (int j = lo; j <= hi; j++) band += __bfloat162float(Kb[(size_t)j * DIM + d]);
    const float* Pb = P + (size_t)b * 4 * DIM;
    float off;
    if (i <= 2048) off = Pb[3 * DIM + d] - band;
    else           off = Pb[(5 - n) * DIM + d];
    float a, bb;
    if (n == 5)      { a = A5; bb = B5; }
    else if (n == 4) { a = A4; bb = B4; }
    else             { a = A3; bb = B3; }
    SK[((size_t)b * SEQ + i) * DIM + d] = __float2bfloat16(a * band + bb * off);
}

// ---------------- LN finalize (stats from fused accumulators) ----------------
__global__ void ln_combine2(const float* __restrict__ sacc, float* __restrict__ stats, int which) {
    double n = (double)TXT_N;
    double mu = (double)sacc[which * 2] / n;
    double var = (double)sacc[which * 2 + 1] / n - mu * mu;
    stats[which * 2]     = (float)mu;
    stats[which * 2 + 1] = (float)(1.0 / sqrt(var + 1e-6));
}

__global__ void ln_apply1_bf(const float* __restrict__ x,
                             const float* __restrict__ g, const float* __restrict__ bta,
                             const float* __restrict__ stats, int which,
                             __nv_bfloat16* __restrict__ out) {
    size_t i = (size_t)blockIdx.x * 256 + threadIdx.x;
    float mu = stats[which * 2], r = stats[which * 2 + 1];
    out[i] = __float2bfloat16((x[i] - mu) * r * g[i] + bta[i]);
}

// final LN apply + image passthrough in one launch
__global__ void ln_apply_final(const float* __restrict__ x,
                               const float* __restrict__ g, const float* __restrict__ bta,
                               const float* __restrict__ stats, int which,
                               float* __restrict__ out,
                               const float* __restrict__ image, float* __restrict__ img_out,
                               int img_n) {
    size_t i = (size_t)blockIdx.x * 256 + threadIdx.x;
    if (i < TXT_N) {
        float mu = stats[which * 2], r = stats[which * 2 + 1];
        out[i] = (x[i] - mu) * r * g[i] + bta[i];
    } else {
        size_t j = i - TXT_N;
        if (j < (size_t)img_n) img_out[j] = image[j];
    }
}

// ---------------- launch ----------------
extern "C" void kernel_launch(void* const* d_in, const int* in_sizes, int n_in,
                              void* d_out, int out_size) {
    const float* text  = (const float*)d_in[0];
    const float* image = (const float*)d_in[1];
    const float* Wq = (const float*)d_in[2];
    const float* bq = (const float*)d_in[3];
    const float* Wk = (const float*)d_in[4];
    const float* bk = (const float*)d_in[5];
    const float* Wv = (const float*)d_in[6];
    const float* bv = (const float*)d_in[7];
    const float* W1 = (const float*)d_in[8];
    const float* b1 = (const float*)d_in[9];
    const float* W2 = (const float*)d_in[10];
    const float* b2 = (const float*)d_in[11];
    const float* gamma = (const float*)d_in[12];
    const float* beta  = (const float*)d_in[13];
    float* out = (float*)d_out;

    float *Osum, *M2sum, *G2, *sacc, *stats, *P, *pp, *vpp, *spp, *Vsum, *sksum, *rowscale, *bqkv;
    __nv_bfloat16 *textbf, *Qbf, *Kbf, *Vbf, *Vtbf, *SKbf, *SKtbf, *Hbf, *FFbf;
    __nv_bfloat16 *Wqkvbf, *W1bf, *W2bf, *G2bf;
    cudaGetSymbolAddress((void**)&textbf, g_textbf);
    cudaGetSymbolAddress((void**)&Qbf,  g_Qbf);
    cudaGetSymbolAddress((void**)&Kbf,  g_Kbf);
    cudaGetSymbolAddress((void**)&Vbf,  g_Vbf);
    cudaGetSymbolAddress((void**)&Vtbf, g_Vtbf);
    cudaGetSymbolAddress((void**)&SKbf, g_SKbf);
    cudaGetSymbolAddress((void**)&SKtbf, g_SKtbf);
    cudaGetSymbolAddress((void**)&Hbf,  g_Hbf);
    cudaGetSymbolAddress((void**)&FFbf, g_FFbf);
    cudaGetSymbolAddress((void**)&Wqkvbf, g_Wqkvbf);
    cudaGetSymbolAddress((void**)&W1bf, g_W1bf);
    cudaGetSymbolAddress((void**)&W2bf, g_W2bf);
    cudaGetSymbolAddress((void**)&G2bf, g_G2bf);
    cudaGetSymbolAddress((void**)&bqkv, g_bqkv);
    cudaGetSymbolAddress((void**)&Osum, g_Osum);
    cudaGetSymbolAddress((void**)&M2sum, g_M2sum);
    cudaGetSymbolAddress((void**)&G2,  g_G2);
    cudaGetSymbolAddress((void**)&sacc, g_sacc);
    cudaGetSymbolAddress((void**)&stats, g_stats);
    cudaGetSymbolAddress((void**)&P,   g_P);
    cudaGetSymbolAddress((void**)&pp,  g_pp);
    cudaGetSymbolAddress((void**)&vpp, g_vpp);
    cudaGetSymbolAddress((void**)&spp, g_spp);
    cudaGetSymbolAddress((void**)&Vsum, g_Vsum);
    cudaGetSymbolAddress((void**)&sksum, g_sksum);
    cudaGetSymbolAddress((void**)&rowscale, g_rowscale);

    static int smem_set = 0;
    if (!smem_set) {
        cudaFuncSetAttribute(bf_gemm, cudaFuncAttributeMaxDynamicSharedMemorySize, BF_SMEM);
        smem_set = 1;
    }

    // sparse-softmax coefficients
    double e = exp(1.0);
    float A[6], Bc[6];
    for (int n = 3; n <= 5; n++) {
        double Z = n * e + (double)(SEQ - n);
        A[n]  = (float)(e / Z);
        Bc[n] = (float)(1.0 / Z);
    }

    // conversions to bf16 (one launch) + zero/bias-concat (one launch)
    convert_all<<<CV_T3 / 256, 256>>>(text, Wq, Wk, Wv, W1, W2,
                                      textbf, Wqkvbf, W1bf, W2bf);
    zero_all<<<(BATCH * DIM * DIM + 255) / 256, 256>>>(G2, sacc, bq, bk, bv, bqkv,
                                                       BATCH * DIM * DIM);

    // fused QKV projection: [16384, 768] routed into Qbf/Kbf/Vbf
    bf_gemm<<<dim3(6, 128, 1), 256, BF_SMEM>>>(textbf, Wqkvbf, Qbf,
        NTOK, 3 * DIM, DIM, DIM, 1, 0, 0, 0,
        1.f, bqkv, 0, 0, nullptr, 0, 1, nullptr, nullptr, Kbf, Vbf, 1);

    // analytic sparse @ K -> SKbf
    prefix_partial<<<dim3(64, BATCH), 256>>>(Kbf, pp);
    prefix_combine<<<BATCH, 256>>>(Kbf, pp, P);
    sk_kernel<<<dim3(SEQ, BATCH), 256>>>(Kbf, P, SKbf, A[3], Bc[3], A[4], Bc[4], A[5], Bc[5]);

    // combined transposes (V, SK) and column sums (Vsum, sksum)
    transpose2_bf<<<dim3(128, 8, 8), dim3(32, 8)>>>(Vbf, Vtbf, SKbf, SKtbf);
    colsum2_partial<<<dim3(32, BATCH), 256>>>(Vbf, SKbf, vpp, spp);
    colsum2_combine<<<BATCH, 256>>>(vpp, spp, Vsum, sksum);

    // rowscale = 1/(SEQ + q.sksum/16)
    rowdiv_kernel<<<NTOK / 8, 256>>>(Qbf, sksum, rowscale);

    // G2[b,e,d] = sum_j V[j,e] SK[j,d]  (split-K=16, atomic fp32), then bf16
    bf_gemm<<<dim3(2, 2, BATCH * 16), 256, BF_SMEM>>>(Vtbf, SKtbf, G2,
        DIM, DIM, SEQ, SEQ / 16, 16,
        (long long)DIM * SEQ, (long long)DIM * SEQ, (long long)DIM * DIM,
        1.f, nullptr, 0, 0, nullptr, 1, 0, nullptr, nullptr, nullptr, nullptr, 0);
    f2bf<<<(BATCH * DIM * DIM + 255) / 256, 256>>>(G2, G2bf, BATCH * DIM * DIM);

    // Osum = (Vsum + Q@G2^T/16)*rowscale + text, with fused LN1 stats
    bf_gemm<<<dim3(2, 32, BATCH), 256, BF_SMEM>>>(Qbf, G2bf, Osum,
        SEQ, DIM, DIM, DIM, 1,
        (long long)SEQ * DIM, (long long)DIM * DIM, (long long)SEQ * DIM,
        0.0625f, Vsum, DIM, 0, rowscale, 0, 0, text, &sacc[0], nullptr, nullptr, 0);

    // LN1 finalize -> Hbf
    ln_combine2<<<1, 1>>>(sacc, stats, 0);
    ln_apply1_bf<<<NTOK, 256>>>(Osum, gamma, beta, stats, 0, Hbf);

    // MLP (bf16 operands, fp32 accumulate); MLP2 fuses +text and LN2 stats
    bf_gemm<<<dim3(8, 128, 1), 256, BF_SMEM>>>(Hbf, W1bf, FFbf, NTOK, DFF, DIM, DIM, 1,
        0, 0, 0, 1.f, b1, 0, 1, nullptr, 0, 1, nullptr, nullptr, nullptr, nullptr, 0);
    bf_gemm<<<dim3(2, 128, 1), 256, BF_SMEM>>>(FFbf, W2bf, M2sum, NTOK, DIM, DFF, DFF, 1,
        0, 0, 0, 1.f, b2, 0, 0, nullptr, 0, 0, text, &sacc[2], nullptr, nullptr, 0);

    // LN2 finalize -> out, with image passthrough fused
    ln_combine2<<<1, 1>>>(sacc, stats, 1);
    int img_n = (out_size >= (int)TXT_N + IMG_N) ? IMG_N : 0;
    ln_apply_final<<<NTOK + (IMG_N + 255) / 256, 256>>>(M2sum, gamma, beta, stats, 1,
                                                        out, image, out + TXT_N, img_n);
}

// round 16
// speedup vs baseline: 1.1593x; 1.0920x over previous
#include <cuda_runtime.h>
#include <cuda_bf16.h>
#include <math.h>
#include <stdint.h>

// ---------------- problem constants ----------------
constexpr int BATCH = 4;
constexpr int SEQ   = 4096;
constexpr int DIM   = 256;
constexpr int DFF   = 1024;
constexpr int NTOK  = BATCH * SEQ;                 // 16384
constexpr size_t TXT_N = (size_t)NTOK * DIM;       // 4,194,304
constexpr int IMG_N = BATCH * 196 * DIM;           // 200,704

// ---------------- scratch (device globals; no allocs allowed) ----------------
__device__ __align__(16) __nv_bfloat16 g_textbf[4194304];
__device__ __align__(16) __nv_bfloat16 g_Qbf [4194304];
__device__ __align__(16) __nv_bfloat16 g_Kbf [4194304];
__device__ __align__(16) __nv_bfloat16 g_Vbf [4194304];
__device__ __align__(16) __nv_bfloat16 g_Vtbf[4194304];
__device__ __align__(16) __nv_bfloat16 g_SKbf[4194304];
__device__ __align__(16) __nv_bfloat16 g_SKtbf[4194304];
__device__ __align__(16) __nv_bfloat16 g_Hbf [4194304];
__device__ __align__(16) __nv_bfloat16 g_FFbf[16777216];
__device__ __align__(16) __nv_bfloat16 g_Wqkvbf[3 * DIM * DIM];   // [768, 256]
__device__ __align__(16) __nv_bfloat16 g_W1bf[DFF * DIM];
__device__ __align__(16) __nv_bfloat16 g_W2bf[DIM * DFF];
__device__ __align__(16) __nv_bfloat16 g_G2bf[BATCH * DIM * DIM];
__device__ float g_bqkv[3 * DIM];
__device__ float g_Osum [4194304];                 // attn + text (fp32)
__device__ float g_M2sum[4194304];                 // mlp + text (fp32)
__device__ float g_G2 [BATCH * DIM * DIM];
__device__ float g_sacc[4];                        // [sum1, ss1, sum2, ss2]
__device__ float g_stats[4];                       // [mu1, r1, mu2, r2]
__device__ float g_P [BATCH * 4 * DIM];
__device__ float g_pp[BATCH * 64 * DIM];
__device__ float g_vpp[BATCH * 32 * DIM];
__device__ float g_spp[BATCH * 32 * DIM];
__device__ float g_Vsum[BATCH * DIM];
__device__ float g_sksum[BATCH * DIM];
__device__ float g_rowscale[NTOK];

// ================= helpers =================
__device__ __forceinline__ uint32_t smem_u32(const void* p) {
    uint32_t a;
    asm("{ .reg .u64 t; cvta.to.shared.u64 t, %1; cvt.u32.u64 %0, t; }" : "=r"(a) : "l"(p));
    return a;
}
#define CP16(dst, src) \
    asm volatile("cp.async.cg.shared.global [%0], [%1], 16;" :: "r"(dst), "l"(src))
#define CP_COMMIT() asm volatile("cp.async.commit_group;" ::: "memory")
#define CP_WAIT(n)  asm volatile("cp.async.wait_group %0;" :: "n"(n) : "memory")
#define LDSM_X4(r, addr) \
    asm volatile("ldmatrix.sync.aligned.m8n8.x4.shared.b16 {%0,%1,%2,%3}, [%4];" \
        : "=r"((r)[0]), "=r"((r)[1]), "=r"((r)[2]), "=r"((r)[3]) : "r"(addr))

// mma.sync m16n8k16 bf16 (row.col): D += A*B
__device__ __forceinline__ void mma16(float* c, uint32_t a0, uint32_t a1,
                                      uint32_t a2, uint32_t a3, uint32_t b0, uint32_t b1) {
    asm volatile(
        "mma.sync.aligned.m16n8k16.row.col.f32.bf16.bf16.f32 "
        "{%0,%1,%2,%3}, {%4,%5,%6,%7}, {%8,%9}, {%0,%1,%2,%3};\n"
        : "+f"(c[0]), "+f"(c[1]), "+f"(c[2]), "+f"(c[3])
        : "r"(a0), "r"(a1), "r"(a2), "r"(a3), "r"(b0), "r"(b1));
}
__device__ __forceinline__ uint32_t pack_bf2(float x, float y) {
    __nv_bfloat162 h = __float22bfloat162_rn(make_float2(x, y));
    return *(uint32_t*)&h;
}

// ================= bf16 tensor-core GEMM (2-stage, ldmatrix operands) =========
constexpr int BFBK = 64;
constexpr int BSTR = 36;                            // words per smem row (32+pad)
constexpr int BF_STAGE = 128 * BSTR * 4;            // 18432
constexpr int BF_SMEM = 4 * BF_STAGE;               // 73728 -> 2 CTAs/SM

__device__ __forceinline__ void load_stage_bf(
    uint32_t smA, uint32_t smB,
    const __nv_bfloat16* __restrict__ Ab, const __nv_bfloat16* __restrict__ Bb,
    int K, int k0, int tid)
{
#pragma unroll
    for (int it = 0; it < 4; it++) {
        int idx = tid + it * 256;                    // 0..1023
        int row = idx >> 3, seg = idx & 7;
        CP16(smA + (uint32_t)(row * BSTR + seg * 4) * 4,
             Ab + (size_t)row * K + k0 + seg * 8);
    }
#pragma unroll
    for (int it = 0; it < 4; it++) {
        int idx = tid + it * 256;
        int row = idx >> 3, seg = idx & 7;
        CP16(smB + (uint32_t)(row * BSTR + seg * 4) * 4,
             Bb + (size_t)row * K + k0 + seg * 8);
    }
}

__global__ void __launch_bounds__(256) bf_gemm(
    const __nv_bfloat16* __restrict__ A, const __nv_bfloat16* __restrict__ B,
    void* __restrict__ C, int M, int N, int K, int Kloc, int kchunks,
    long long sA, long long sB, long long sC,
    float alpha, const float* __restrict__ bias, long long sBias, int relu,
    const float* __restrict__ rowscale, int atomic_out, int out_bf,
    const float* __restrict__ resid, float* __restrict__ stats_acc,
    void* __restrict__ C2, void* __restrict__ C3, int qkv)
{
    extern __shared__ char smem[];
    const int tid = threadIdx.x;
    const int wid = tid >> 5, lane = tid & 31;
    const int wm = wid & 3, wn = wid >> 2;
    const int g = lane >> 2, tg = lane & 3, t2 = tg << 1;
    const int bx = blockIdx.x, by = blockIdx.y;
    const int bz = blockIdx.z / kchunks;
    const int kc = blockIdx.z % kchunks;
    const int m0 = by * 128, n0 = bx * 128;
    const __nv_bfloat16* Ab = A + (size_t)bz * sA + (size_t)m0 * K + (size_t)kc * Kloc;
    const __nv_bfloat16* Bb = B + (size_t)bz * sB + (size_t)n0 * K + (size_t)kc * Kloc;

    const uint32_t sbase = smem_u32(smem);
    const int lrow8  = lane & 7;
    const int a_row  = lrow8 + ((lane >> 3) & 1) * 8;
    const int a_colw = ((lane >> 4) & 1) * 4;
    uint32_t a_off[2];
#pragma unroll
    for (int i = 0; i < 2; i++)
        a_off[i] = (uint32_t)((wm * 32 + i * 16 + a_row) * BSTR + a_colw) * 4;
    const int b_row  = lrow8 + ((lane >> 4) & 1) * 8;
    const int b_colw = ((lane >> 3) & 1) * 4;
    uint32_t b_off[4];
#pragma unroll
    for (int p = 0; p < 4; p++)
        b_off[p] = (uint32_t)((wn * 64 + p * 16 + b_row) * BSTR + b_colw) * 4;

    float acc[2][8][4];
#pragma unroll
    for (int i = 0; i < 2; i++)
#pragma unroll
        for (int j = 0; j < 8; j++)
#pragma unroll
            for (int v = 0; v < 4; v++) acc[i][j][v] = 0.f;

    const int KT = Kloc / BFBK;
    load_stage_bf(sbase, sbase + 2 * BF_STAGE, Ab, Bb, K, 0, tid);
    CP_COMMIT();

    for (int kt = 0; kt < KT; kt++) {
        const int cur = kt & 1;
        if (kt + 1 < KT) {
            load_stage_bf(sbase + (cur ^ 1) * BF_STAGE, sbase + (2 + (cur ^ 1)) * BF_STAGE,
                          Ab, Bb, K, (kt + 1) * BFBK, tid);
            CP_COMMIT();
            CP_WAIT(1);
        } else {
            CP_WAIT(0);
        }
        __syncthreads();

        const uint32_t aBase = sbase + (uint32_t)cur * BF_STAGE;
        const uint32_t bBase = sbase + (uint32_t)(2 + cur) * BF_STAGE;
#pragma unroll
        for (int step = 0; step < 4; step++) {
            const uint32_t so = (uint32_t)step * 32;
            uint32_t afr[2][4];
            LDSM_X4(afr[0], aBase + a_off[0] + so);
            LDSM_X4(afr[1], aBase + a_off[1] + so);
            uint32_t bfr[4][4];
#pragma unroll
            for (int p = 0; p < 4; p++)
                LDSM_X4(bfr[p], bBase + b_off[p] + so);
#pragma unroll
            for (int p = 0; p < 4; p++) {
#pragma unroll
                for (int i = 0; i < 2; i++) {
                    mma16(acc[i][2 * p],     afr[i][0], afr[i][1], afr[i][2], afr[i][3],
                          bfr[p][0], bfr[p][1]);
                    mma16(acc[i][2 * p + 1], afr[i][0], afr[i][1], afr[i][2], afr[i][3],
                          bfr[p][2], bfr[p][3]);
                }
            }
        }
        __syncthreads();
    }

    const float* bp = bias ? bias + (size_t)bz * sBias : nullptr;
    const float* rs = rowscale ? rowscale + (size_t)bz * M : nullptr;
    const float* rp = resid ? resid + (size_t)bz * sC : nullptr;
    float lsum = 0.f, lss = 0.f;
#pragma unroll
    for (int i = 0; i < 2; i++) {
        int r = m0 + wm * 32 + i * 16 + g;
#pragma unroll
        for (int j = 0; j < 8; j++) {
            int c = n0 + wn * 64 + j * 8 + t2;
            float2 v0, v1;
            v0.x = acc[i][j][0] * alpha; v0.y = acc[i][j][1] * alpha;
            v1.x = acc[i][j][2] * alpha; v1.y = acc[i][j][3] * alpha;
            if (bp) {
                float bb0 = __ldg(bp + c), bb1 = __ldg(bp + c + 1);
                v0.x += bb0; v0.y += bb1;
                v1.x += bb0; v1.y += bb1;
            }
            if (relu) {
                v0.x = fmaxf(v0.x, 0.f); v0.y = fmaxf(v0.y, 0.f);
                v1.x = fmaxf(v1.x, 0.f); v1.y = fmaxf(v1.y, 0.f);
            }
            if (rs) {
                float s0 = rs[r], s1 = rs[r + 8];
                v0.x *= s0; v0.y *= s0;
                v1.x *= s1; v1.y *= s1;
            }
            if (rp) {
                v0.x += __ldg(rp + (size_t)r * N + c);
                v0.y += __ldg(rp + (size_t)r * N + c + 1);
                v1.x += __ldg(rp + (size_t)(r + 8) * N + c);
                v1.y += __ldg(rp + (size_t)(r + 8) * N + c + 1);
                lsum += v0.x + v0.y + v1.x + v1.y;
                lss  += v0.x * v0.x + v0.y * v0.y + v1.x * v1.x + v1.y * v1.y;
            }
            if (atomic_out) {
                float* Cb = (float*)C + (size_t)bz * sC;
                atomicAdd(Cb + (size_t)r * N + c,     v0.x);
                atomicAdd(Cb + (size_t)r * N + c + 1, v0.y);
                atomicAdd(Cb + (size_t)(r + 8) * N + c,     v1.x);
                atomicAdd(Cb + (size_t)(r + 8) * N + c + 1, v1.y);
            } else if (out_bf) {
                void* base = C;
                int Nout = N, cc = c;
                if (qkv) {
                    int sel = c >> 8;
                    base = (sel == 0) ? C : (sel == 1) ? C2 : C3;
                    Nout = 256;
                    cc = c & 255;
                }
                uint32_t* cb = (uint32_t*)((__nv_bfloat16*)base + (size_t)bz * sC);
                cb[((size_t)r * Nout + cc) >> 1]       = pack_bf2(v0.x, v0.y);
                cb[((size_t)(r + 8) * Nout + cc) >> 1] = pack_bf2(v1.x, v1.y);
            } else {
                float* Cb = (float*)C + (size_t)bz * sC;
                *(float2*)(Cb + (size_t)r * N + c)       = v0;
                *(float2*)(Cb + (size_t)(r + 8) * N + c) = v1;
            }
        }
    }
    if (stats_acc) {
        __shared__ float s_sum[256], s_ss[256];
        s_sum[tid] = lsum; s_ss[tid] = lss;
        __syncthreads();
        for (int o = 128; o; o >>= 1) {
            if (tid < o) { s_sum[tid] += s_sum[tid + o]; s_ss[tid] += s_ss[tid + o]; }
            __syncthreads();
        }
        if (tid == 0) {
            atomicAdd(&stats_acc[0], s_sum[0]);
            atomicAdd(&stats_acc[1], s_ss[0]);
        }
    }
}

// ---------------- batched fp32 -> bf16 conversions (vectorized, one launch) ----
constexpr int CV_T0 = 4194304;                       // text
constexpr int CV_T1 = CV_T0 + 3 * 65536;             // Wq|Wk|Wv -> Wqkv
constexpr int CV_T2 = CV_T1 + 262144;                // W1
constexpr int CV_T3 = CV_T2 + 262144;                // W2 (total 4915200)

__global__ void convert_all(
    const float* __restrict__ text, const float* __restrict__ Wq,
    const float* __restrict__ Wk, const float* __restrict__ Wv,
    const float* __restrict__ W1, const float* __restrict__ W2,
    __nv_bfloat16* __restrict__ textbf, __nv_bfloat16* __restrict__ Wqkvbf,
    __nv_bfloat16* __restrict__ W1bf, __nv_bfloat16* __restrict__ W2bf)
{
    int i = (blockIdx.x * 256 + threadIdx.x) * 4;
    const float* src;
    __nv_bfloat16* dst;
    int j;
    if (i < CV_T0)      { src = text; dst = textbf; j = i; }
    else if (i < CV_T1) {
        j = i - CV_T0;
        src = (j < 65536) ? Wq : (j < 131072) ? Wk : Wv;
        dst = Wqkvbf;
        // note: source index within its own 65536 block
        float4 v = *(const float4*)(src + (j & 65535));
        uint2 o;
        o.x = pack_bf2(v.x, v.y); o.y = pack_bf2(v.z, v.w);
        *(uint2*)(dst + j) = o;
        return;
    }
    else if (i < CV_T2) { src = W1; dst = W1bf; j = i - CV_T1; src += j; dst += j; j = 0;
        float4 v = *(const float4*)src;
        uint2 o; o.x = pack_bf2(v.x, v.y); o.y = pack_bf2(v.z, v.w);
        *(uint2*)dst = o; return; }
    else if (i < CV_T3) { src = W2; dst = W2bf; j = i - CV_T2; src += j; dst += j;
        float4 v = *(const float4*)src;
        uint2 o; o.x = pack_bf2(v.x, v.y); o.y = pack_bf2(v.z, v.w);
        *(uint2*)dst = o; return; }
    else return;
    float4 v = *(const float4*)(src + j);
    uint2 o;
    o.x = pack_bf2(v.x, v.y); o.y = pack_bf2(v.z, v.w);
    *(uint2*)(dst + j) = o;
}

__global__ void f2bf(const float* __restrict__ src, __nv_bfloat16* __restrict__ dst, int n) {
    int i = (blockIdx.x * 256 + threadIdx.x) * 4;
    if (i < n) {
        float4 v = *(const float4*)(src + i);
        uint2 o;
        o.x = pack_bf2(v.x, v.y); o.y = pack_bf2(v.z, v.w);
        *(uint2*)(dst + i) = o;
    }
}

// zero G2 + stats accumulators + build concatenated qkv bias (one launch)
__global__ void zero_all(float* __restrict__ G2, float* __restrict__ sacc,
                         const float* __restrict__ bq, const float* __restrict__ bk,
                         const float* __restrict__ bv, float* __restrict__ bqkv, int nG2) {
    int i = blockIdx.x * 256 + threadIdx.x;
    if (i < nG2) G2[i] = 0.f;
    if (i < 4) sacc[i] = 0.f;
    if (i < 3 * DIM) {
        const float* src = (i < DIM) ? bq : (i < 2 * DIM) ? bk : bv;
        bqkv[i] = src[i & (DIM - 1)];
    }
}

// ---------------- combined bf16 transpose (V and SK in one launch) ----------
__global__ void transpose2_bf(const __nv_bfloat16* __restrict__ V,
                              __nv_bfloat16* __restrict__ Vt,
                              const __nv_bfloat16* __restrict__ SK,
                              __nv_bfloat16* __restrict__ SKt) {
    __shared__ __nv_bfloat16 t[32][34];
    int zb = blockIdx.z;
    int b = zb & 3;
    const __nv_bfloat16* X = (zb < 4) ? V : SK;
    __nv_bfloat16* Xt = (zb < 4) ? Vt : SKt;
    int s0 = blockIdx.x * 32, d0 = blockIdx.y * 32;
    const __nv_bfloat16* Xb = X + (size_t)b * SEQ * DIM;
    __nv_bfloat16* Xtb = Xt + (size_t)b * SEQ * DIM;
    int x = threadIdx.x, y = threadIdx.y;
#pragma unroll
    for (int i = 0; i < 32; i += 8)
        t[y + i][x] = Xb[(size_t)(s0 + y + i) * DIM + d0 + x];
    __syncthreads();
#pragma unroll
    for (int i = 0; i < 32; i += 8)
        Xtb[(size_t)(d0 + y + i) * SEQ + s0 + x] = t[x][y + i];
}

// ---------------- combined column sums (4-acc unroll) -------------------------
__global__ void colsum2_partial(const __nv_bfloat16* __restrict__ V,
                                const __nv_bfloat16* __restrict__ SK,
                                float* __restrict__ vpp, float* __restrict__ spp) {
    int ch = blockIdx.x, b = blockIdx.y, d = threadIdx.x;
    const __nv_bfloat16* Vb = V + (size_t)b * SEQ * DIM + d;
    const __nv_bfloat16* Sb = SK + (size_t)b * SEQ * DIM + d;
    float sv0 = 0.f, sv1 = 0.f, sv2 = 0.f, sv3 = 0.f;
    float ss0 = 0.f, ss1 = 0.f, ss2 = 0.f, ss3 = 0.f;
    int s0 = ch * 128;
#pragma unroll 4
    for (int s = s0; s < s0 + 128; s += 4) {
        sv0 += __bfloat162float(Vb[(size_t)s * DIM]);
        sv1 += __bfloat162float(Vb[(size_t)(s + 1) * DIM]);
        sv2 += __bfloat162float(Vb[(size_t)(s + 2) * DIM]);
        sv3 += __bfloat162float(Vb[(size_t)(s + 3) * DIM]);
        ss0 += __bfloat162float(Sb[(size_t)s * DIM]);
        ss1 += __bfloat162float(Sb[(size_t)(s + 1) * DIM]);
        ss2 += __bfloat162float(Sb[(size_t)(s + 2) * DIM]);
        ss3 += __bfloat162float(Sb[(size_t)(s + 3) * DIM]);
    }
    vpp[((size_t)b * 32 + ch) * DIM + d] = (sv0 + sv1) + (sv2 + sv3);
    spp[((size_t)b * 32 + ch) * DIM + d] = (ss0 + ss1) + (ss2 + ss3);
}
__global__ void colsum2_combine(const float* __restrict__ vpp, const float* __restrict__ spp,
                                float* __restrict__ Vsum, float* __restrict__ sksum) {
    int b = blockIdx.x, d = threadIdx.x;
    float sv = 0.f, ss = 0.f;
    for (int ch = 0; ch < 32; ch++) {
        sv += vpp[((size_t)b * 32 + ch) * DIM + d];
        ss += spp[((size_t)b * 32 + ch) * DIM + d];
    }
    Vsum[b * DIM + d] = sv;
    sksum[b * DIM + d] = ss;
}

// ---------------- rowscale = 1/(SEQ + q.sksum/16), q in bf16 ---------
__global__ void rowdiv_kernel(const __nv_bfloat16* __restrict__ Q,
                              const float* __restrict__ sksum,
                              float* __restrict__ rowscale) {
    int wid = threadIdx.x >> 5, lane = threadIdx.x & 31;
    int row = blockIdx.x * 8 + wid;
    int b = row >> 12;
    const uint32_t* q = (const uint32_t*)(Q + (size_t)row * DIM);
    const float* sk = sksum + b * DIM;
    float s = 0.f;
#pragma unroll
    for (int k = 0; k < 4; k++) {
        int w = lane + k * 32;
        __nv_bfloat162 h = *(const __nv_bfloat162*)&q[w];
        s += __bfloat162float(h.x) * sk[2 * w] + __bfloat162float(h.y) * sk[2 * w + 1];
    }
#pragma unroll
    for (int o = 16; o; o >>= 1) s += __shfl_xor_sync(0xffffffffu, s, o);
    if (lane == 0) rowscale[row] = 1.f / ((float)SEQ + s * 0.0625f);
}

// ---------------- prefix sums of K rows (4-acc unroll) -------------------------
__global__ void prefix_partial(const __nv_bfloat16* __restrict__ Kmat, float* __restrict__ pp) {
    int ch = blockIdx.x, b = blockIdx.y, d = threadIdx.x;   // 64 chunks of 32 rows
    int s0 = ch * 32;
    int s1 = min(s0 + 32, 2047);
    const __nv_bfloat16* Kb = Kmat + (size_t)b * SEQ * DIM + d;
    float a0 = 0.f, a1 = 0.f, a2 = 0.f, a3 = 0.f;
    int ss = s0;
    for (; ss + 4 <= s1; ss += 4) {
        a0 += __bfloat162float(Kb[(size_t)ss * DIM]);
        a1 += __bfloat162float(Kb[(size_t)(ss + 1) * DIM]);
        a2 += __bfloat162float(Kb[(size_t)(ss + 2) * DIM]);
        a3 += __bfloat162float(Kb[(size_t)(ss + 3) * DIM]);
    }
    for (; ss < s1; ss++) a0 += __bfloat162float(Kb[(size_t)ss * DIM]);
    pp[((size_t)b * 64 + ch) * DIM + d] = (a0 + a1) + (a2 + a3);
}

__global__ void prefix_combine(const __nv_bfloat16* __restrict__ Kmat,
                               const float* __restrict__ pp, float* __restrict__ P) {
    int b = blockIdx.x, d = threadIdx.x;
    const __nv_bfloat16* Kb = Kmat + (size_t)b * SEQ * DIM;
    float s = 0.f;
    for (int ch = 0; ch < 64; ch++) s += pp[((size_t)b * 64 + ch) * DIM + d];
    float p2047 = s;
    float p2048 = p2047 + __bfloat162float(Kb[(size_t)2047 * DIM + d]);
    float p2049 = p2048 + __bfloat162float(Kb[(size_t)2048 * DIM + d]);
    float p2052 = p2049 + __bfloat162float(Kb[(size_t)2049 * DIM + d])
                        + __bfloat162float(Kb[(size_t)2050 * DIM + d])
                        + __bfloat162float(Kb[(size_t)2051 * DIM + d]);
    float* Pb = P + (size_t)b * 4 * DIM;
    Pb[0 * DIM + d] = p2047;
    Pb[1 * DIM + d] = p2048;
    Pb[2 * DIM + d] = p2049;
    Pb[3 * DIM + d] = p2052;
}

// sk_kernel in bf16x2 lanes: 128 threads, each handles 2 columns
__global__ void sk_kernel(const __nv_bfloat16* __restrict__ Kmat, const float* __restrict__ P,
                          __nv_bfloat16* __restrict__ SK,
                          float A3, float B3, float A4, float B4, float A5, float B5) {
    int i = blockIdx.x, b = blockIdx.y, d2 = threadIdx.x;   // d2: 0..127 (word)
    const uint32_t* Kb = (const uint32_t*)(Kmat + (size_t)b * SEQ * DIM) + d2;
    int lo = max(i - 2, 0), hi = min(i + 2, SEQ - 1);
    int n = hi - lo + 1;
    float band_x = 0.f, band_y = 0.f;
    for (int j = lo; j <= hi; j++) {
        __nv_bfloat162 h = *(const __nv_bfloat162*)&Kb[(size_t)j * (DIM / 2)];
        band_x += __bfloat162float(h.x);
        band_y += __bfloat162float(h.y);
    }
    const float* Pb = P + (size_t)b * 4 * DIM;
    float off_x, off_y;
    int dd = d2 * 2;
    if (i <= 2048) {
        float2 p = *(const float2*)&Pb[3 * DIM + dd];
        off_x = p.x - band_x;
        off_y = p.y - band_y;
    } else {
        float2 p = *(const float2*)&Pb[(5 - n) * DIM + dd];
        off_x = p.x;
        off_y = p.y;
    }
    float a, bb;
    if (n == 5)      { a = A5; bb = B5; }
    else if (n == 4) { a = A4; bb = B4; }
    else             { a = A3; bb = B3; }
    uint32_t* dst = (uint32_t*)(SK + ((size_t)b * SEQ + i) * DIM) + d2;
    *dst = pack_bf2(a * band_x + bb * off_x, a * band_y + bb * off_y);
}

// ---------------- LN finalize (stats from fused accumulators) ----------------
__global__ void ln_combine2(const float* __restrict__ sacc, float* __restrict__ stats, int which) {
    double n = (double)TXT_N;
    double mu = (double)sacc[which * 2] / n;
    double var = (double)sacc[which * 2 + 1] / n - mu * mu;
    stats[which * 2]     = (float)mu;
    stats[which * 2 + 1] = (float)(1.0 / sqrt(var + 1e-6));
}

// vectorized: 4 elements per thread
__global__ void ln_apply1_bf(const float* __restrict__ x,
                             const float* __restrict__ g, const float* __restrict__ bta,
                             const float* __restrict__ stats, int which,
                             __nv_bfloat16* __restrict__ out) {
    size_t i = ((size_t)blockIdx.x * 256 + threadIdx.x) * 4;
    float mu = stats[which * 2], r = stats[which * 2 + 1];
    float4 xv = *(const float4*)(x + i);
    float4 gv = *(const float4*)(g + i);
    float4 bv = *(const float4*)(bta + i);
    uint2 o;
    o.x = pack_bf2((xv.x - mu) * r * gv.x + bv.x, (xv.y - mu) * r * gv.y + bv.y);
    o.y = pack_bf2((xv.z - mu) * r * gv.z + bv.z, (xv.w - mu) * r * gv.w + bv.w);
    *(uint2*)(out + i) = o;
}

// final LN apply + image passthrough, vectorized
__global__ void ln_apply_final(const float* __restrict__ x,
                               const float* __restrict__ g, const float* __restrict__ bta,
                               const float* __restrict__ stats, int which,
                               float* __restrict__ out,
                               const float* __restrict__ image, float* __restrict__ img_out,
                               int img_n) {
    size_t i = ((size_t)blockIdx.x * 256 + threadIdx.x) * 4;
    if (i < TXT_N) {
        float mu = stats[which * 2], r = stats[which * 2 + 1];
        float4 xv = *(const float4*)(x + i);
        float4 gv = *(const float4*)(g + i);
        float4 bv = *(const float4*)(bta + i);
        float4 o;
        o.x = (xv.x - mu) * r * gv.x + bv.x;
        o.y = (xv.y - mu) * r * gv.y + bv.y;
        o.z = (xv.z - mu) * r * gv.z + bv.z;
        o.w = (xv.w - mu) * r * gv.w + bv.w;
        *(float4*)(out + i) = o;
    } else {
        size_t j = i - TXT_N;
        if (j < (size_t)img_n) {
            *(float4*)(img_out + j) = *(const float4*)(image + j);
        }
    }
}

// ---------------- launch ----------------
extern "C" void kernel_launch(void* const* d_in, const int* in_sizes, int n_in,
                              void* d_out, int out_size) {
    const float* text  = (const float*)d_in[0];
    const float* image = (const float*)d_in[1];
    const float* Wq = (const float*)d_in[2];
    const float* bq = (const float*)d_in[3];
    const float* Wk = (const float*)d_in[4];
    const float* bk = (const float*)d_in[5];
    const float* Wv = (const float*)d_in[6];
    const float* bv = (const float*)d_in[7];
    const float* W1 = (const float*)d_in[8];
    const float* b1 = (const float*)d_in[9];
    const float* W2 = (const float*)d_in[10];
    const float* b2 = (const float*)d_in[11];
    const float* gamma = (const float*)d_in[12];
    const float* beta  = (const float*)d_in[13];
    float* out = (float*)d_out;

    float *Osum, *M2sum, *G2, *sacc, *stats, *P, *pp, *vpp, *spp, *Vsum, *sksum, *rowscale, *bqkv;
    __nv_bfloat16 *textbf, *Qbf, *Kbf, *Vbf, *Vtbf, *SKbf, *SKtbf, *Hbf, *FFbf;
    __nv_bfloat16 *Wqkvbf, *W1bf, *W2bf, *G2bf;
    cudaGetSymbolAddress((void**)&textbf, g_textbf);
    cudaGetSymbolAddress((void**)&Qbf,  g_Qbf);
    cudaGetSymbolAddress((void**)&Kbf,  g_Kbf);
    cudaGetSymbolAddress((void**)&Vbf,  g_Vbf);
    cudaGetSymbolAddress((void**)&Vtbf, g_Vtbf);
    cudaGetSymbolAddress((void**)&SKbf, g_SKbf);
    cudaGetSymbolAddress((void**)&SKtbf, g_SKtbf);
    cudaGetSymbolAddress((void**)&Hbf,  g_Hbf);
    cudaGetSymbolAddress((void**)&FFbf, g_FFbf);
    cudaGetSymbolAddress((void**)&Wqkvbf, g_Wqkvbf);
    cudaGetSymbolAddress((void**)&W1bf, g_W1bf);
    cudaGetSymbolAddress((void**)&W2bf, g_W2bf);
    cudaGetSymbolAddress((void**)&G2bf, g_G2bf);
    cudaGetSymbolAddress((void**)&bqkv, g_bqkv);
    cudaGetSymbolAddress((void**)&Osum, g_Osum);
    cudaGetSymbolAddress((void**)&M2sum, g_M2sum);
    cudaGetSymbolAddress((void**)&G2,  g_G2);
    cudaGetSymbolAddress((void**)&sacc, g_sacc);
    cudaGetSymbolAddress((void**)&stats, g_stats);
    cudaGetSymbolAddress((void**)&P,   g_P);
    cudaGetSymbolAddress((void**)&pp,  g_pp);
    cudaGetSymbolAddress((void**)&vpp, g_vpp);
    cudaGetSymbolAddress((void**)&spp, g_spp);
    cudaGetSymbolAddress((void**)&Vsum, g_Vsum);
    cudaGetSymbolAddress((void**)&sksum, g_sksum);
    cudaGetSymbolAddress((void**)&rowscale, g_rowscale);

    static int smem_set = 0;
    if (!smem_set) {
        cudaFuncSetAttribute(bf_gemm, cudaFuncAttributeMaxDynamicSharedMemorySize, BF_SMEM);
        smem_set = 1;
    }

    // sparse-softmax coefficients
    double e = exp(1.0);
    float A[6], Bc[6];
    for (int n = 3; n <= 5; n++) {
        double Z = n * e + (double)(SEQ - n);
        A[n]  = (float)(e / Z);
        Bc[n] = (float)(1.0 / Z);
    }

    // conversions to bf16 (one vectorized launch) + zero/bias-concat
    convert_all<<<CV_T3 / 1024, 256>>>(text, Wq, Wk, Wv, W1, W2,
                                       textbf, Wqkvbf, W1bf, W2bf);
    zero_all<<<(BATCH * DIM * DIM + 255) / 256, 256>>>(G2, sacc, bq, bk, bv, bqkv,
                                                       BATCH * DIM * DIM);

    // fused QKV projection: [16384, 768] routed into Qbf/Kbf/Vbf
    bf_gemm<<<dim3(6, 128, 1), 256, BF_SMEM>>>(textbf, Wqkvbf, Qbf,
        NTOK, 3 * DIM, DIM, DIM, 1, 0, 0, 0,
        1.f, bqkv, 0, 0, nullptr, 0, 1, nullptr, nullptr, Kbf, Vbf, 1);

    // analytic sparse @ K -> SKbf
    prefix_partial<<<dim3(64, BATCH), 256>>>(Kbf, pp);
    prefix_combine<<<BATCH, 256>>>(Kbf, pp, P);
    sk_kernel<<<dim3(SEQ, BATCH), 128>>>(Kbf, P, SKbf, A[3], Bc[3], A[4], Bc[4], A[5], Bc[5]);

    // combined transposes (V, SK) and column sums (Vsum, sksum)
    transpose2_bf<<<dim3(128, 8, 8), dim3(32, 8)>>>(Vbf, Vtbf, SKbf, SKtbf);
    colsum2_partial<<<dim3(32, BATCH), 256>>>(Vbf, SKbf, vpp, spp);
    colsum2_combine<<<BATCH, 256>>>(vpp, spp, Vsum, sksum);

    // rowscale = 1/(SEQ + q.sksum/16)
    rowdiv_kernel<<<NTOK / 8, 256>>>(Qbf, sksum, rowscale);

    // G2[b,e,d] = sum_j V[j,e] SK[j,d]  (split-K=16, atomic fp32), then bf16
    bf_gemm<<<dim3(2, 2, BATCH * 16), 256, BF_SMEM>>>(Vtbf, SKtbf, G2,
        DIM, DIM, SEQ, SEQ / 16, 16,
        (long long)DIM * SEQ, (long long)DIM * SEQ, (long long)DIM * DIM,
        1.f, nullptr, 0, 0, nullptr, 1, 0, nullptr, nullptr, nullptr, nullptr, 0);
    f2bf<<<(BATCH * DIM * DIM + 1023) / 1024, 256>>>(G2, G2bf, BATCH * DIM * DIM);

    // Osum = (Vsum + Q@G2^T/16)*rowscale + text, with fused LN1 stats
    bf_gemm<<<dim3(2, 32, BATCH), 256, BF_SMEM>>>(Qbf, G2bf, Osum,
        SEQ, DIM, DIM, DIM, 1,
        (long long)SEQ * DIM, (long long)DIM * DIM, (long long)SEQ * DIM,
        0.0625f, Vsum, DIM, 0, rowscale, 0, 0, text, &sacc[0], nullptr, nullptr, 0);

    // LN1 finalize -> Hbf
    ln_combine2<<<1, 1>>>(sacc, stats, 0);
    ln_apply1_bf<<<(int)(TXT_N / 1024), 256>>>(Osum, gamma, beta, stats, 0, Hbf);

    // MLP (bf16 operands, fp32 accumulate); MLP2 fuses +text and LN2 stats
    bf_gemm<<<dim3(8, 128, 1), 256, BF_SMEM>>>(Hbf, W1bf, FFbf, NTOK, DFF, DIM, DIM, 1,
        0, 0, 0, 1.f, b1, 0, 1, nullptr, 0, 1, nullptr, nullptr, nullptr, nullptr, 0);
    bf_gemm<<<dim3(2, 128, 1), 256, BF_SMEM>>>(FFbf, W2bf, M2sum, NTOK, DIM, DFF, DFF, 1,
        0, 0, 0, 1.f, b2, 0, 0, nullptr, 0, 0, text, &sacc[2], nullptr, nullptr, 0);

    // LN2 finalize -> out, with image passthrough fused (vectorized)
    ln_combine2<<<1, 1>>>(sacc, stats, 1);
    int img_n = (out_size >= (int)TXT_N + IMG_N) ? IMG_N : 0;
    ln_apply_final<<<(int)(TXT_N / 1024) + (IMG_N / 4 + 255) / 256, 256>>>(
        M2sum, gamma, beta, stats, 1, out, image, out + TXT_N, img_n);
}